// round 2
// baseline (speedup 1.0000x reference)
#include <cuda_runtime.h>
#include <math.h>

// Problem constants
constexpr int T_   = 512;
constexpr int B_   = 64;
constexpr int DIN_ = 1024;
constexpr int H_   = 1024;
constexpr size_t TBH = (size_t)T_ * B_ * H_;   // 33,554,432
constexpr int BH = B_ * H_;                    // 65,536

constexpr int NCTA = 128;       // persistent scan CTAs (<= 148 SMs, all co-resident)
constexpr int NTHR = 256;
constexpr int JPC  = 8;         // output columns owned per CTA (128*8 = 1024)

// ---------------- device scratch (static; no runtime allocation) ----------------
__device__ float g_xproj[3ULL * TBH];   // Xr, Xz, Xh pre-activations
__device__ float g_Rh[BH];              // R * h (global, consumed by all CTAs)
__device__ int            g_count = 0;  // grid barrier arrival counter
__device__ volatile int   g_phase = 0;  // grid barrier phase (monotonic)

// ---------------- Phase 1: input projections  C[g] = X @ W_x{g} + b_{g} ----------------
__global__ __launch_bounds__(256) void proj_kernel(
    const float* __restrict__ X,
    const float* __restrict__ W0, const float* __restrict__ W1, const float* __restrict__ W2,
    const float* __restrict__ b0, const float* __restrict__ b1, const float* __restrict__ b2)
{
    constexpr int BM = 128, BN = 128, BK = 8, TM = 8, TN = 8;
    const int g = blockIdx.z;
    const float* __restrict__ W    = (g == 0) ? W0 : ((g == 1) ? W1 : W2);
    const float* __restrict__ bias = (g == 0) ? b0 : ((g == 1) ? b1 : b2);
    float* __restrict__ C = g_xproj + (size_t)g * TBH;

    const int m0 = blockIdx.y * BM;
    const int n0 = blockIdx.x * BN;

    __shared__ float As[BK][BM];
    __shared__ float Bs[BK][BN];

    const int tid  = threadIdx.x;
    const int tcol = tid & 15;
    const int trow = tid >> 4;

    float acc[TM][TN];
#pragma unroll
    for (int i = 0; i < TM; i++)
#pragma unroll
        for (int j = 0; j < TN; j++) acc[i][j] = 0.f;

    const int aRow = tid >> 1, aCol = (tid & 1) * 4;
    const int bRow = tid >> 5, bCol = (tid & 31) * 4;

    for (int k0 = 0; k0 < DIN_; k0 += BK) {
        float4 a = *(const float4*)(X + (size_t)(m0 + aRow) * DIN_ + k0 + aCol);
        As[aCol + 0][aRow] = a.x;
        As[aCol + 1][aRow] = a.y;
        As[aCol + 2][aRow] = a.z;
        As[aCol + 3][aRow] = a.w;
        float4 bv = *(const float4*)(W + (size_t)(k0 + bRow) * H_ + n0 + bCol);
        *(float4*)&Bs[bRow][bCol] = bv;
        __syncthreads();

#pragma unroll
        for (int kk = 0; kk < BK; kk++) {
            float ar[TM], br[TN];
#pragma unroll
            for (int i = 0; i < TM; i++) ar[i] = As[kk][trow * TM + i];
#pragma unroll
            for (int j = 0; j < TN; j++) br[j] = Bs[kk][tcol * TN + j];
#pragma unroll
            for (int i = 0; i < TM; i++)
#pragma unroll
                for (int j = 0; j < TN; j++) acc[i][j] += ar[i] * br[j];
        }
        __syncthreads();
    }

#pragma unroll
    for (int i = 0; i < TM; i++) {
        const int m = m0 + trow * TM + i;
#pragma unroll
        for (int j = 0; j < TN; j += 4) {
            const int n = n0 + tcol * TN + j;
            float4 v;
            v.x = acc[i][j + 0] + bias[n + 0];
            v.y = acc[i][j + 1] + bias[n + 1];
            v.z = acc[i][j + 2] + bias[n + 2];
            v.w = acc[i][j + 3] + bias[n + 3];
            *(float4*)(C + (size_t)m * H_ + n) = v;
        }
    }
}

// ---------------- grid-wide barrier (all NCTA CTAs co-resident) ----------------
__device__ __forceinline__ void grid_barrier(int target)
{
    __threadfence();          // make this thread's global writes visible GPU-wide
    __syncthreads();          // CTA-scope release of all threads' writes to tid 0
    if (threadIdx.x == 0) {
        int prev = atomicAdd(&g_count, 1);
        if (prev == NCTA - 1) {
            g_count = 0;
            __threadfence();
            g_phase = target;                 // release the pack
        } else {
            while (g_phase < target) { __nanosleep(64); }
        }
    }
    __syncthreads();          // CTA-scope acquire for all threads
}

// ---------------- Phase 2: persistent recurrent scan ----------------
// smem layout (dynamic):
//   Wall [1024][24]  : cols 0-7 = W_hr slice, 8-15 = W_hz, 16-23 = W_hh (persistent)
//   hs   [64][67]    : staged 64-wide K chunk of h (or R*h)
//   red  [4096]      : split-K partial sums
//   zs   [64][8]     : update gate Z for this CTA's columns
constexpr int W_FLOATS  = 1024 * 24;
constexpr int HS_PITCH  = 67;
constexpr int HS_FLOATS = 64 * HS_PITCH;
constexpr int RED_FLOATS = 4096;
constexpr int ZS_FLOATS  = 512;
constexpr int SMEM_FLOATS = W_FLOATS + HS_FLOATS + RED_FLOATS + ZS_FLOATS;
constexpr size_t SMEM_BYTES = (size_t)SMEM_FLOATS * sizeof(float);

__global__ __launch_bounds__(NTHR, 1) void scan_kernel(
    const float* __restrict__ state,
    const float* __restrict__ W_hr, const float* __restrict__ W_hz,
    const float* __restrict__ W_hh,
    float* __restrict__ out)
{
    extern __shared__ float smem[];
    float* Wall = smem;
    float* hs   = Wall + W_FLOATS;
    float* red  = hs + HS_FLOATS;
    float* zs   = red + RED_FLOATS;
    __shared__ int s_base;

    const int tid = threadIdx.x;
    const int cta = blockIdx.x;
    const int j0  = cta * JPC;

    // Load this CTA's 24 weight columns into smem (persistent for all steps).
    for (int idx = tid; idx < 1024 * 8; idx += NTHR) {
        const int k = idx >> 3, jj = idx & 7;
        Wall[k * 24 + 0  + jj] = W_hr[(size_t)k * H_ + j0 + jj];
        Wall[k * 24 + 8  + jj] = W_hz[(size_t)k * H_ + j0 + jj];
        Wall[k * 24 + 16 + jj] = W_hh[(size_t)k * H_ + j0 + jj];
    }
    if (tid == 0) s_base = g_phase;
    __syncthreads();
    const int base = s_base;

    // Phase A thread mapping: seg sA (4 x K/4), 16 b-quads, 4 j-quads
    const int sA = tid >> 6;          // 0..3
    const int posA = tid & 63;
    const int bqA = posA >> 2;        // 0..15
    const int jgA = posA & 3;         // 0..3  -> cols jgA*4 .. +3 of [r0-7|z0-7]
    // Phase B thread mapping: seg sB (8), 16 b-quads, 2 j-quads
    const int sB = tid >> 5;          // 0..7
    const int posB = tid & 31;
    const int bqB = posB >> 1;        // 0..15
    const int jgB = posB & 1;         // 0..1

    for (int t = 0; t < T_; t++) {
        const float* __restrict__ h_in = (t == 0) ? state : (out + (size_t)(t - 1) * BH);

        // ================= Phase A: R and Z gates =================
        float acc[16];
#pragma unroll
        for (int i = 0; i < 16; i++) acc[i] = 0.f;

        for (int c = 0; c < 16; c++) {
            const int k0 = c * 64;
            // stage h[0..63][k0..k0+63] into hs[b][kk]
#pragma unroll
            for (int r = 0; r < 4; r++) {
                const int q = tid + NTHR * r;       // 0..1023 float4 units
                const int b = q >> 4, qq = (q & 15) * 4;
                float4 v = *(const float4*)(h_in + (size_t)b * H_ + k0 + qq);
                hs[b * HS_PITCH + qq + 0] = v.x;
                hs[b * HS_PITCH + qq + 1] = v.y;
                hs[b * HS_PITCH + qq + 2] = v.z;
                hs[b * HS_PITCH + qq + 3] = v.w;
            }
            __syncthreads();
#pragma unroll
            for (int kk2 = 0; kk2 < 16; kk2++) {
                const int kk = sA * 16 + kk2;
                const float4 wv = *(const float4*)&Wall[(k0 + kk) * 24 + jgA * 4];
                const float h0 = hs[(bqA * 4 + 0) * HS_PITCH + kk];
                const float h1 = hs[(bqA * 4 + 1) * HS_PITCH + kk];
                const float h2 = hs[(bqA * 4 + 2) * HS_PITCH + kk];
                const float h3 = hs[(bqA * 4 + 3) * HS_PITCH + kk];
                acc[0]  += h0 * wv.x; acc[1]  += h0 * wv.y; acc[2]  += h0 * wv.z; acc[3]  += h0 * wv.w;
                acc[4]  += h1 * wv.x; acc[5]  += h1 * wv.y; acc[6]  += h1 * wv.z; acc[7]  += h1 * wv.w;
                acc[8]  += h2 * wv.x; acc[9]  += h2 * wv.y; acc[10] += h2 * wv.z; acc[11] += h2 * wv.w;
                acc[12] += h3 * wv.x; acc[13] += h3 * wv.y; acc[14] += h3 * wv.z; acc[15] += h3 * wv.w;
            }
            __syncthreads();
        }
        // write split-K partials: red[sA][b*16 + col]
#pragma unroll
        for (int i = 0; i < 4; i++)
#pragma unroll
            for (int jj = 0; jj < 4; jj++)
                red[sA * 1024 + (bqA * 4 + i) * 16 + jgA * 4 + jj] = acc[i * 4 + jj];
        __syncthreads();

        // reduce + gate epilogue (1024 outputs, 4 per thread)
        {
            const float* __restrict__ Xr_t = g_xproj + 0 * TBH + (size_t)t * BH;
            const float* __restrict__ Xz_t = g_xproj + 1 * TBH + (size_t)t * BH;
#pragma unroll
            for (int oo = 0; oo < 4; oo++) {
                const int o = tid * 4 + oo;
                const float sum = red[o] + red[1024 + o] + red[2048 + o] + red[3072 + o];
                const int b = o >> 4, col = o & 15;
                const int j = j0 + (col & 7);
                if (col < 8) {
                    const float pre = sum + Xr_t[(size_t)b * H_ + j];
                    const float R = 1.f / (1.f + __expf(-pre));
                    g_Rh[b * H_ + j] = R * h_in[(size_t)b * H_ + j];
                } else {
                    const float pre = sum + Xz_t[(size_t)b * H_ + j];
                    zs[b * 8 + (col & 7)] = 1.f / (1.f + __expf(-pre));
                }
            }
        }
        grid_barrier(base + 2 * t + 1);   // g_Rh complete everywhere

        // ================= Phase B: candidate + state update =================
        float acc2[16];
#pragma unroll
        for (int i = 0; i < 16; i++) acc2[i] = 0.f;

        for (int c = 0; c < 16; c++) {
            const int k0 = c * 64;
#pragma unroll
            for (int r = 0; r < 4; r++) {
                const int q = tid + NTHR * r;
                const int b = q >> 4, qq = (q & 15) * 4;
                float4 v = *(const float4*)(g_Rh + (size_t)b * H_ + k0 + qq);
                hs[b * HS_PITCH + qq + 0] = v.x;
                hs[b * HS_PITCH + qq + 1] = v.y;
                hs[b * HS_PITCH + qq + 2] = v.z;
                hs[b * HS_PITCH + qq + 3] = v.w;
            }
            __syncthreads();
#pragma unroll
            for (int kk2 = 0; kk2 < 8; kk2++) {
                const int kk = sB * 8 + kk2;
                const float4 wv = *(const float4*)&Wall[(k0 + kk) * 24 + 16 + jgB * 4];
                const float h0 = hs[(bqB * 4 + 0) * HS_PITCH + kk];
                const float h1 = hs[(bqB * 4 + 1) * HS_PITCH + kk];
                const float h2 = hs[(bqB * 4 + 2) * HS_PITCH + kk];
                const float h3 = hs[(bqB * 4 + 3) * HS_PITCH + kk];
                acc2[0]  += h0 * wv.x; acc2[1]  += h0 * wv.y; acc2[2]  += h0 * wv.z; acc2[3]  += h0 * wv.w;
                acc2[4]  += h1 * wv.x; acc2[5]  += h1 * wv.y; acc2[6]  += h1 * wv.z; acc2[7]  += h1 * wv.w;
                acc2[8]  += h2 * wv.x; acc2[9]  += h2 * wv.y; acc2[10] += h2 * wv.z; acc2[11] += h2 * wv.w;
                acc2[12] += h3 * wv.x; acc2[13] += h3 * wv.y; acc2[14] += h3 * wv.z; acc2[15] += h3 * wv.w;
            }
            __syncthreads();
        }
        // partials: red[sB][b*8 + jc]
#pragma unroll
        for (int i = 0; i < 4; i++)
#pragma unroll
            for (int jj = 0; jj < 4; jj++)
                red[sB * 512 + (bqB * 4 + i) * 8 + jgB * 4 + jj] = acc2[i * 4 + jj];
        __syncthreads();

        // reduce + candidate/update epilogue (512 outputs, 2 per thread)
        {
            const float* __restrict__ Xh_t = g_xproj + 2 * TBH + (size_t)t * BH;
            float* __restrict__ out_t = out + (size_t)t * BH;
#pragma unroll
            for (int oo = 0; oo < 2; oo++) {
                const int o = tid * 2 + oo;
                float sum = 0.f;
#pragma unroll
                for (int s = 0; s < 8; s++) sum += red[s * 512 + o];
                const int b = o >> 3, jc = o & 7;
                const int j = j0 + jc;
                const float pre  = sum + Xh_t[(size_t)b * H_ + j];
                const float hhat = tanhf(pre);
                const float z    = zs[b * 8 + jc];
                const float hv   = h_in[(size_t)b * H_ + j];
                out_t[(size_t)b * H_ + j] = z * hv + (1.f - z) * hhat;
            }
        }
        grid_barrier(base + 2 * t + 2);   // out[t] complete everywhere
    }
}

// ---------------- host launcher ----------------
extern "C" void kernel_launch(void* const* d_in, const int* in_sizes, int n_in,
                              void* d_out, int out_size)
{
    (void)in_sizes; (void)n_in; (void)out_size;
    const float* X     = (const float*)d_in[0];
    const float* state = (const float*)d_in[1];
    const float* W_xr  = (const float*)d_in[2];
    const float* W_hr  = (const float*)d_in[3];
    const float* b_r   = (const float*)d_in[4];
    const float* W_xz  = (const float*)d_in[5];
    const float* W_hz  = (const float*)d_in[6];
    const float* b_z   = (const float*)d_in[7];
    const float* W_xh  = (const float*)d_in[8];
    const float* W_hh  = (const float*)d_in[9];
    const float* b_h   = (const float*)d_in[10];
    float* out = (float*)d_out;

    // Phase 1: input projections (bias fused).
    {
        dim3 grid(H_ / 128, (T_ * B_) / 128, 3);
        proj_kernel<<<grid, 256>>>(X, W_xr, W_xz, W_xh, b_r, b_z, b_h);
    }

    // Phase 2: single persistent scan kernel (2 graph nodes total so far).
    static int smem_set = 0;
    if (!smem_set) {
        cudaFuncSetAttribute(scan_kernel,
                             cudaFuncAttributeMaxDynamicSharedMemorySize,
                             (int)SMEM_BYTES);
        smem_set = 1;
    }
    scan_kernel<<<NCTA, NTHR, SMEM_BYTES>>>(state, W_hr, W_hz, W_hh, out);

    // final_state = outputs[T-1]
    cudaMemcpyAsync(out + TBH, out + TBH - BH, (size_t)BH * sizeof(float),
                    cudaMemcpyDeviceToDevice, 0);
}

// round 6
// speedup vs baseline: 1.4846x; 1.4846x over previous
#include <cuda_runtime.h>
#include <math.h>

// Problem constants
constexpr int T_   = 512;
constexpr int B_   = 64;
constexpr int DIN_ = 1024;
constexpr int H_   = 1024;
constexpr size_t TBH = (size_t)T_ * B_ * H_;   // 33,554,432
constexpr int BH = B_ * H_;                    // 65,536

constexpr int NCTA = 128;       // persistent scan CTAs (<= 148 SMs, all co-resident)
constexpr int NTHR = 256;
constexpr int JPC  = 8;         // output columns owned per CTA (128*8 = 1024)

// ---------------- device scratch (static; no runtime allocation) ----------------
__device__ float g_xproj[3ULL * TBH];   // Xr, Xz, Xh pre-activations
__device__ float g_Rh[BH];              // R * h (global, consumed by all CTAs)
__device__ int            g_count = 0;  // grid barrier arrival counter
__device__ volatile int   g_phase = 0;  // grid barrier phase (monotonic)

// ---------------- Phase 1: input projections  C[g] = X @ W_x{g} + b_{g} ----------------
__global__ __launch_bounds__(256) void proj_kernel(
    const float* __restrict__ X,
    const float* __restrict__ W0, const float* __restrict__ W1, const float* __restrict__ W2,
    const float* __restrict__ b0, const float* __restrict__ b1, const float* __restrict__ b2)
{
    constexpr int BM = 128, BN = 128, BK = 8, TM = 8, TN = 8;
    const int g = blockIdx.z;
    const float* __restrict__ W    = (g == 0) ? W0 : ((g == 1) ? W1 : W2);
    const float* __restrict__ bias = (g == 0) ? b0 : ((g == 1) ? b1 : b2);
    float* __restrict__ C = g_xproj + (size_t)g * TBH;

    const int m0 = blockIdx.y * BM;
    const int n0 = blockIdx.x * BN;

    __shared__ float As[BK][BM];
    __shared__ float Bs[BK][BN];

    const int tid  = threadIdx.x;
    const int tcol = tid & 15;
    const int trow = tid >> 4;

    float acc[TM][TN];
#pragma unroll
    for (int i = 0; i < TM; i++)
#pragma unroll
        for (int j = 0; j < TN; j++) acc[i][j] = 0.f;

    const int aRow = tid >> 1, aCol = (tid & 1) * 4;
    const int bRow = tid >> 5, bCol = (tid & 31) * 4;

    for (int k0 = 0; k0 < DIN_; k0 += BK) {
        float4 a = *(const float4*)(X + (size_t)(m0 + aRow) * DIN_ + k0 + aCol);
        As[aCol + 0][aRow] = a.x;
        As[aCol + 1][aRow] = a.y;
        As[aCol + 2][aRow] = a.z;
        As[aCol + 3][aRow] = a.w;
        float4 bv = *(const float4*)(W + (size_t)(k0 + bRow) * H_ + n0 + bCol);
        *(float4*)&Bs[bRow][bCol] = bv;
        __syncthreads();

#pragma unroll
        for (int kk = 0; kk < BK; kk++) {
            float ar[TM], br[TN];
#pragma unroll
            for (int i = 0; i < TM; i++) ar[i] = As[kk][trow * TM + i];
#pragma unroll
            for (int j = 0; j < TN; j++) br[j] = Bs[kk][tcol * TN + j];
#pragma unroll
            for (int i = 0; i < TM; i++)
#pragma unroll
                for (int j = 0; j < TN; j++) acc[i][j] += ar[i] * br[j];
        }
        __syncthreads();
    }

#pragma unroll
    for (int i = 0; i < TM; i++) {
        const int m = m0 + trow * TM + i;
#pragma unroll
        for (int j = 0; j < TN; j += 4) {
            const int n = n0 + tcol * TN + j;
            float4 v;
            v.x = acc[i][j + 0] + bias[n + 0];
            v.y = acc[i][j + 1] + bias[n + 1];
            v.z = acc[i][j + 2] + bias[n + 2];
            v.w = acc[i][j + 3] + bias[n + 3];
            *(float4*)(C + (size_t)m * H_ + n) = v;
        }
    }
}

// ---------------- grid-wide barrier (all NCTA CTAs co-resident) ----------------
__device__ __forceinline__ void grid_barrier(int target)
{
    __threadfence();          // make this thread's global writes visible GPU-wide
    __syncthreads();          // CTA-scope release of all threads' writes to tid 0
    if (threadIdx.x == 0) {
        int prev = atomicAdd(&g_count, 1);
        if (prev == NCTA - 1) {
            g_count = 0;
            __threadfence();
            g_phase = target;                 // release the pack
        } else {
            while (g_phase < target) { __nanosleep(64); }
        }
    }
    __syncthreads();          // CTA-scope acquire for all threads
}

// ---------------- Phase 2: persistent recurrent scan ----------------
// smem layout (dynamic):
//   Wall [1024][24]  : cols 0-7 = W_hr slice, 8-15 = W_hz, 16-23 = W_hh (persistent)
//   hs   [64][67]    : staged 64-wide K chunk of h (or R*h)
//   red  [4096]      : split-K partial sums
//   zs   [64][8]     : update gate Z for this CTA's columns
constexpr int W_FLOATS  = 1024 * 24;
constexpr int HS_PITCH  = 67;
constexpr int HS_FLOATS = 64 * HS_PITCH;
constexpr int RED_FLOATS = 4096;
constexpr int ZS_FLOATS  = 512;
constexpr int SMEM_FLOATS = W_FLOATS + HS_FLOATS + RED_FLOATS + ZS_FLOATS;
constexpr size_t SMEM_BYTES = (size_t)SMEM_FLOATS * sizeof(float);

__global__ __launch_bounds__(NTHR, 1) void scan_kernel(
    const float* __restrict__ state,
    const float* __restrict__ W_hr, const float* __restrict__ W_hz,
    const float* __restrict__ W_hh,
    float* __restrict__ out)
{
    extern __shared__ float smem[];
    float* Wall = smem;
    float* hs   = Wall + W_FLOATS;
    float* red  = hs + HS_FLOATS;
    float* zs   = red + RED_FLOATS;
    __shared__ int s_base;

    const int tid = threadIdx.x;
    const int cta = blockIdx.x;
    const int j0  = cta * JPC;

    // Load this CTA's 24 weight columns into smem (persistent for all steps).
    for (int idx = tid; idx < 1024 * 8; idx += NTHR) {
        const int k = idx >> 3, jj = idx & 7;
        Wall[k * 24 + 0  + jj] = W_hr[(size_t)k * H_ + j0 + jj];
        Wall[k * 24 + 8  + jj] = W_hz[(size_t)k * H_ + j0 + jj];
        Wall[k * 24 + 16 + jj] = W_hh[(size_t)k * H_ + j0 + jj];
    }
    if (tid == 0) s_base = g_phase;
    __syncthreads();
    const int base = s_base;

    // Phase A thread mapping: seg sA (4 x K/4), 16 b-quads, 4 j-quads
    const int sA = tid >> 6;          // 0..3
    const int posA = tid & 63;
    const int bqA = posA >> 2;        // 0..15
    const int jgA = posA & 3;         // 0..3  -> cols jgA*4 .. +3 of [r0-7|z0-7]
    // Phase B thread mapping: seg sB (8), 16 b-quads, 2 j-quads
    const int sB = tid >> 5;          // 0..7
    const int posB = tid & 31;
    const int bqB = posB >> 1;        // 0..15
    const int jgB = posB & 1;         // 0..1

    for (int t = 0; t < T_; t++) {
        const float* __restrict__ h_in = (t == 0) ? state : (out + (size_t)(t - 1) * BH);

        // ================= Phase A: R and Z gates =================
        float acc[16];
#pragma unroll
        for (int i = 0; i < 16; i++) acc[i] = 0.f;

        for (int c = 0; c < 16; c++) {
            const int k0 = c * 64;
            // stage h[0..63][k0..k0+63] into hs[b][kk]
#pragma unroll
            for (int r = 0; r < 4; r++) {
                const int q = tid + NTHR * r;       // 0..1023 float4 units
                const int b = q >> 4, qq = (q & 15) * 4;
                float4 v = *(const float4*)(h_in + (size_t)b * H_ + k0 + qq);
                hs[b * HS_PITCH + qq + 0] = v.x;
                hs[b * HS_PITCH + qq + 1] = v.y;
                hs[b * HS_PITCH + qq + 2] = v.z;
                hs[b * HS_PITCH + qq + 3] = v.w;
            }
            __syncthreads();
#pragma unroll
            for (int kk2 = 0; kk2 < 16; kk2++) {
                const int kk = sA * 16 + kk2;
                const float4 wv = *(const float4*)&Wall[(k0 + kk) * 24 + jgA * 4];
                const float h0 = hs[(bqA * 4 + 0) * HS_PITCH + kk];
                const float h1 = hs[(bqA * 4 + 1) * HS_PITCH + kk];
                const float h2 = hs[(bqA * 4 + 2) * HS_PITCH + kk];
                const float h3 = hs[(bqA * 4 + 3) * HS_PITCH + kk];
                acc[0]  += h0 * wv.x; acc[1]  += h0 * wv.y; acc[2]  += h0 * wv.z; acc[3]  += h0 * wv.w;
                acc[4]  += h1 * wv.x; acc[5]  += h1 * wv.y; acc[6]  += h1 * wv.z; acc[7]  += h1 * wv.w;
                acc[8]  += h2 * wv.x; acc[9]  += h2 * wv.y; acc[10] += h2 * wv.z; acc[11] += h2 * wv.w;
                acc[12] += h3 * wv.x; acc[13] += h3 * wv.y; acc[14] += h3 * wv.z; acc[15] += h3 * wv.w;
            }
            __syncthreads();
        }
        // write split-K partials: red[sA][b*16 + col]
#pragma unroll
        for (int i = 0; i < 4; i++)
#pragma unroll
            for (int jj = 0; jj < 4; jj++)
                red[sA * 1024 + (bqA * 4 + i) * 16 + jgA * 4 + jj] = acc[i * 4 + jj];
        __syncthreads();

        // reduce + gate epilogue (1024 outputs, 4 per thread)
        {
            const float* __restrict__ Xr_t = g_xproj + 0 * TBH + (size_t)t * BH;
            const float* __restrict__ Xz_t = g_xproj + 1 * TBH + (size_t)t * BH;
#pragma unroll
            for (int oo = 0; oo < 4; oo++) {
                const int o = tid * 4 + oo;
                const float sum = red[o] + red[1024 + o] + red[2048 + o] + red[3072 + o];
                const int b = o >> 4, col = o & 15;
                const int j = j0 + (col & 7);
                if (col < 8) {
                    const float pre = sum + Xr_t[(size_t)b * H_ + j];
                    const float R = 1.f / (1.f + __expf(-pre));
                    g_Rh[b * H_ + j] = R * h_in[(size_t)b * H_ + j];
                } else {
                    const float pre = sum + Xz_t[(size_t)b * H_ + j];
                    zs[b * 8 + (col & 7)] = 1.f / (1.f + __expf(-pre));
                }
            }
        }
        grid_barrier(base + 2 * t + 1);   // g_Rh complete everywhere

        // ================= Phase B: candidate + state update =================
        float acc2[16];
#pragma unroll
        for (int i = 0; i < 16; i++) acc2[i] = 0.f;

        for (int c = 0; c < 16; c++) {
            const int k0 = c * 64;
#pragma unroll
            for (int r = 0; r < 4; r++) {
                const int q = tid + NTHR * r;
                const int b = q >> 4, qq = (q & 15) * 4;
                float4 v = *(const float4*)(g_Rh + (size_t)b * H_ + k0 + qq);
                hs[b * HS_PITCH + qq + 0] = v.x;
                hs[b * HS_PITCH + qq + 1] = v.y;
                hs[b * HS_PITCH + qq + 2] = v.z;
                hs[b * HS_PITCH + qq + 3] = v.w;
            }
            __syncthreads();
#pragma unroll
            for (int kk2 = 0; kk2 < 8; kk2++) {
                const int kk = sB * 8 + kk2;
                const float4 wv = *(const float4*)&Wall[(k0 + kk) * 24 + 16 + jgB * 4];
                const float h0 = hs[(bqB * 4 + 0) * HS_PITCH + kk];
                const float h1 = hs[(bqB * 4 + 1) * HS_PITCH + kk];
                const float h2 = hs[(bqB * 4 + 2) * HS_PITCH + kk];
                const float h3 = hs[(bqB * 4 + 3) * HS_PITCH + kk];
                acc2[0]  += h0 * wv.x; acc2[1]  += h0 * wv.y; acc2[2]  += h0 * wv.z; acc2[3]  += h0 * wv.w;
                acc2[4]  += h1 * wv.x; acc2[5]  += h1 * wv.y; acc2[6]  += h1 * wv.z; acc2[7]  += h1 * wv.w;
                acc2[8]  += h2 * wv.x; acc2[9]  += h2 * wv.y; acc2[10] += h2 * wv.z; acc2[11] += h2 * wv.w;
                acc2[12] += h3 * wv.x; acc2[13] += h3 * wv.y; acc2[14] += h3 * wv.z; acc2[15] += h3 * wv.w;
            }
            __syncthreads();
        }
        // partials: red[sB][b*8 + jc]
#pragma unroll
        for (int i = 0; i < 4; i++)
#pragma unroll
            for (int jj = 0; jj < 4; jj++)
                red[sB * 512 + (bqB * 4 + i) * 8 + jgB * 4 + jj] = acc2[i * 4 + jj];
        __syncthreads();

        // reduce + candidate/update epilogue (512 outputs, 2 per thread)
        {
            const float* __restrict__ Xh_t = g_xproj + 2 * TBH + (size_t)t * BH;
            float* __restrict__ out_t = out + (size_t)t * BH;
#pragma unroll
            for (int oo = 0; oo < 2; oo++) {
                const int o = tid * 2 + oo;
                float sum = 0.f;
#pragma unroll
                for (int s = 0; s < 8; s++) sum += red[s * 512 + o];
                const int b = o >> 3, jc = o & 7;
                const int j = j0 + jc;
                const float pre  = sum + Xh_t[(size_t)b * H_ + j];
                const float hhat = tanhf(pre);
                const float z    = zs[b * 8 + jc];
                const float hv   = h_in[(size_t)b * H_ + j];
                out_t[(size_t)b * H_ + j] = z * hv + (1.f - z) * hhat;
            }
        }
        grid_barrier(base + 2 * t + 2);   // out[t] complete everywhere
    }
}

// ---------------- host launcher ----------------
extern "C" void kernel_launch(void* const* d_in, const int* in_sizes, int n_in,
                              void* d_out, int out_size)
{
    (void)in_sizes; (void)n_in; (void)out_size;
    const float* X     = (const float*)d_in[0];
    const float* state = (const float*)d_in[1];
    const float* W_xr  = (const float*)d_in[2];
    const float* W_hr  = (const float*)d_in[3];
    const float* b_r   = (const float*)d_in[4];
    const float* W_xz  = (const float*)d_in[5];
    const float* W_hz  = (const float*)d_in[6];
    const float* b_z   = (const float*)d_in[7];
    const float* W_xh  = (const float*)d_in[8];
    const float* W_hh  = (const float*)d_in[9];
    const float* b_h   = (const float*)d_in[10];
    float* out = (float*)d_out;

    // Phase 1: input projections (bias fused).
    {
        dim3 grid(H_ / 128, (T_ * B_) / 128, 3);
        proj_kernel<<<grid, 256>>>(X, W_xr, W_xz, W_xh, b_r, b_z, b_h);
    }

    // Phase 2: single persistent scan kernel (2 graph nodes total so far).
    static int smem_set = 0;
    if (!smem_set) {
        cudaFuncSetAttribute(scan_kernel,
                             cudaFuncAttributeMaxDynamicSharedMemorySize,
                             (int)SMEM_BYTES);
        smem_set = 1;
    }
    scan_kernel<<<NCTA, NTHR, SMEM_BYTES>>>(state, W_hr, W_hz, W_hh, out);

    // final_state = outputs[T-1]
    cudaMemcpyAsync(out + TBH, out + TBH - BH, (size_t)BH * sizeof(float),
                    cudaMemcpyDeviceToDevice, 0);
}

// round 10
// speedup vs baseline: 1.8834x; 1.2687x over previous
#include <cuda_runtime.h>
#include <cuda_bf16.h>
#include <math.h>
#include <stdint.h>

// ---------------- problem constants ----------------
constexpr int T_   = 512;
constexpr int B_   = 64;
constexpr int DIN_ = 1024;
constexpr int H_   = 1024;
constexpr size_t TBH = (size_t)T_ * B_ * H_;
constexpr int BH = B_ * H_;

constexpr int NCTA = 128;
constexpr int NTHR = 256;

// ---------------- device scratch ----------------
__device__ float         g_xproj[3ULL * TBH];
__device__ __nv_bfloat16 g_h_bf[64 * 2048];    // [b][ hi(1024) | lo(1024) ]
__device__ __nv_bfloat16 g_rh_bf[64 * 2048];   // R*h split
__device__ int           g_count = 0;
__device__ volatile int  g_phase = 0;

// ---------------- smem layout (bytes) ----------------
// B fragments are stored in the exact mma.sync m16n8k16 per-lane layout:
//   [ntile][kstep][lane] -> 2x u32 (8 bytes)
constexpr uint32_t BGH   = 0;          // gates B hi:  [2][64][32]*8 = 32768
constexpr uint32_t BGL   = 32768;      // gates B lo
constexpr uint32_t BCH   = 65536;      // cand  B hi:  [64][32]*8    = 16384
constexpr uint32_t BCL   = 81920;      // cand  B lo
constexpr uint32_t AB0   = 98304;      // A stage buf0 (hi then lo)
constexpr uint32_t ABSTR = 34816;      // per-buffer stride (hi 17408 + lo 17408)
constexpr uint32_t AHALF = 17408;      // lo offset inside a buffer
constexpr uint32_t ZB    = 167936;     // Z gate values: 64*8*4 = 2048
constexpr uint32_t RED   = 169984;     // phase-B split-K partials: 4*32*16 = 2048 (pad 4096)
constexpr uint32_t SMEM_TOTAL = 174080;
constexpr int APITCH = 136;            // staged A row pitch in bf16 elems (odd 16B units -> conflict-free)

// ---------------- helpers ----------------
__device__ __forceinline__ float sigf(float x) { return 1.f / (1.f + __expf(-x)); }

__device__ __forceinline__ uint32_t pack2(float a, float b, uint32_t& lo) {
    __nv_bfloat16 ah = __float2bfloat16(a), bh = __float2bfloat16(b);
    __nv_bfloat16 al = __float2bfloat16(a - __bfloat162float(ah));
    __nv_bfloat16 bl = __float2bfloat16(b - __bfloat162float(bh));
    lo = (uint32_t)__bfloat16_as_ushort(al) | ((uint32_t)__bfloat16_as_ushort(bl) << 16);
    return (uint32_t)__bfloat16_as_ushort(ah) | ((uint32_t)__bfloat16_as_ushort(bh) << 16);
}

__device__ __forceinline__ void mma_bf16(float* d, const uint32_t* a, const uint2& b) {
    asm volatile(
        "mma.sync.aligned.m16n8k16.row.col.f32.bf16.bf16.f32 "
        "{%0,%1,%2,%3}, {%4,%5,%6,%7}, {%8,%9}, {%0,%1,%2,%3};"
        : "+f"(d[0]), "+f"(d[1]), "+f"(d[2]), "+f"(d[3])
        : "r"(a[0]), "r"(a[1]), "r"(a[2]), "r"(a[3]), "r"(b.x), "r"(b.y));
}

__device__ __forceinline__ void cp16(uint32_t saddr, const void* gptr) {
    asm volatile("cp.async.cg.shared.global [%0], [%1], 16;" :: "r"(saddr), "l"(gptr));
}

// ---------------- Phase 1: input projections (unchanged, known-good) ----------------
__global__ __launch_bounds__(256) void proj_kernel(
    const float* __restrict__ X,
    const float* __restrict__ W0, const float* __restrict__ W1, const float* __restrict__ W2,
    const float* __restrict__ b0, const float* __restrict__ b1, const float* __restrict__ b2)
{
    constexpr int BM = 128, BN = 128, BK = 8, TM = 8, TN = 8;
    const int g = blockIdx.z;
    const float* __restrict__ W    = (g == 0) ? W0 : ((g == 1) ? W1 : W2);
    const float* __restrict__ bias = (g == 0) ? b0 : ((g == 1) ? b1 : b2);
    float* __restrict__ C = g_xproj + (size_t)g * TBH;

    const int m0 = blockIdx.y * BM;
    const int n0 = blockIdx.x * BN;

    __shared__ float As[BK][BM];
    __shared__ float Bs[BK][BN];

    const int tid  = threadIdx.x;
    const int tcol = tid & 15;
    const int trow = tid >> 4;

    float acc[TM][TN];
#pragma unroll
    for (int i = 0; i < TM; i++)
#pragma unroll
        for (int j = 0; j < TN; j++) acc[i][j] = 0.f;

    const int aRow = tid >> 1, aCol = (tid & 1) * 4;
    const int bRow = tid >> 5, bCol = (tid & 31) * 4;

    for (int k0 = 0; k0 < DIN_; k0 += BK) {
        float4 a = *(const float4*)(X + (size_t)(m0 + aRow) * DIN_ + k0 + aCol);
        As[aCol + 0][aRow] = a.x;
        As[aCol + 1][aRow] = a.y;
        As[aCol + 2][aRow] = a.z;
        As[aCol + 3][aRow] = a.w;
        float4 bv = *(const float4*)(W + (size_t)(k0 + bRow) * H_ + n0 + bCol);
        *(float4*)&Bs[bRow][bCol] = bv;
        __syncthreads();

#pragma unroll
        for (int kk = 0; kk < BK; kk++) {
            float ar[TM], br[TN];
#pragma unroll
            for (int i = 0; i < TM; i++) ar[i] = As[kk][trow * TM + i];
#pragma unroll
            for (int j = 0; j < TN; j++) br[j] = Bs[kk][tcol * TN + j];
#pragma unroll
            for (int i = 0; i < TM; i++)
#pragma unroll
                for (int j = 0; j < TN; j++) acc[i][j] += ar[i] * br[j];
        }
        __syncthreads();
    }

#pragma unroll
    for (int i = 0; i < TM; i++) {
        const int m = m0 + trow * TM + i;
#pragma unroll
        for (int j = 0; j < TN; j += 4) {
            const int n = n0 + tcol * TN + j;
            float4 v;
            v.x = acc[i][j + 0] + bias[n + 0];
            v.y = acc[i][j + 1] + bias[n + 1];
            v.z = acc[i][j + 2] + bias[n + 2];
            v.w = acc[i][j + 3] + bias[n + 3];
            *(float4*)(C + (size_t)m * H_ + n) = v;
        }
    }
}

// ---------------- grid barrier (proven) ----------------
__device__ __forceinline__ void grid_barrier(int target)
{
    __threadfence();
    __syncthreads();
    if (threadIdx.x == 0) {
        int prev = atomicAdd(&g_count, 1);
        if (prev == NCTA - 1) {
            g_count = 0;
            __threadfence();
            g_phase = target;
        } else {
            while (g_phase < target) { __nanosleep(64); }
        }
    }
    __syncthreads();
}

// ---------------- streamed HMMA mainloop ----------------
// A = src[64][2048] bf16 ([hi|lo] per row), streamed in 8 chunks of 128 K-cols,
// cp.async double-buffered.  3-term split accumulation into acc[4] (m16n8 f32).
// PHASE 0 (gates): all warps active; warp w -> m-tile (w&3), n-tile (w>>2); B at BGH/BGL.
// PHASE 1 (cand):  warp w -> m-tile (w&3), active on chunks with parity (w>>2); B at BCH/BCL.
template<int PHASE>
__device__ __forceinline__ void run_mainloop(char* sm, uint32_t sb, int tid,
                                             const __nv_bfloat16* __restrict__ src,
                                             float* acc)
{
    const int w = tid >> 5, lane = tid & 31;
    const int g = lane >> 2, c = lane & 3;
    const int m = w & 3;
    const int sel = w >> 2;
    const int arow = m * 16 + g;
    const int b = tid >> 2, q = tid & 3;   // staging role

    // prefetch chunk 0
    {
        const __nv_bfloat16* gp = src + (size_t)b * 2048 + q * 32;
        uint32_t ad = sb + AB0 + (uint32_t)((b * APITCH + q * 32) * 2);
#pragma unroll
        for (int u = 0; u < 4; u++) {
            cp16(ad + u * 16, gp + u * 8);
            cp16(ad + AHALF + u * 16, gp + 1024 + u * 8);
        }
        asm volatile("cp.async.commit_group;");
    }

    for (int chunk = 0; chunk < 8; chunk++) {
        if (chunk < 7) {
            const __nv_bfloat16* gp = src + (size_t)b * 2048 + (chunk + 1) * 128 + q * 32;
            uint32_t ad = sb + AB0 + (uint32_t)(((chunk + 1) & 1)) * ABSTR
                        + (uint32_t)((b * APITCH + q * 32) * 2);
#pragma unroll
            for (int u = 0; u < 4; u++) {
                cp16(ad + u * 16, gp + u * 8);
                cp16(ad + AHALF + u * 16, gp + 1024 + u * 8);
            }
            asm volatile("cp.async.commit_group;");
            asm volatile("cp.async.wait_group 1;");
        } else {
            asm volatile("cp.async.wait_group 0;");
        }
        __syncthreads();

        const bool active = (PHASE == 0) ? true : ((chunk & 1) == sel);
        if (active) {
            const char* AH = sm + AB0 + (uint32_t)(chunk & 1) * ABSTR;
            const uint32_t bb_hi = (PHASE == 0) ? (BGH + (uint32_t)sel * 16384u) : BCH;
            const uint32_t bb_lo = (PHASE == 0) ? (BGL + (uint32_t)sel * 16384u) : BCL;
#pragma unroll
            for (int s = 0; s < 8; s++) {
                const int sg = chunk * 8 + s;
                const char* ap = AH + (size_t)(arow * APITCH + s * 16 + 2 * c) * 2;
                uint32_t ah[4], al[4];
                ah[0] = *(const uint32_t*)ap;
                ah[1] = *(const uint32_t*)(ap + APITCH * 16);       // +8 rows
                ah[2] = *(const uint32_t*)(ap + 16);                // +8 k
                ah[3] = *(const uint32_t*)(ap + APITCH * 16 + 16);
                const char* alp = ap + AHALF;
                al[0] = *(const uint32_t*)alp;
                al[1] = *(const uint32_t*)(alp + APITCH * 16);
                al[2] = *(const uint32_t*)(alp + 16);
                al[3] = *(const uint32_t*)(alp + APITCH * 16 + 16);
                uint2 bh = *(const uint2*)(sm + bb_hi + (size_t)(sg * 32 + lane) * 8);
                uint2 bl = *(const uint2*)(sm + bb_lo + (size_t)(sg * 32 + lane) * 8);
                mma_bf16(acc, ah, bh);
                mma_bf16(acc, ah, bl);
                mma_bf16(acc, al, bh);
            }
        }
        __syncthreads();
    }
}

// ---------------- Phase 2: persistent HMMA scan ----------------
__global__ __launch_bounds__(NTHR, 1) void scan_kernel(
    const float* __restrict__ state,
    const float* __restrict__ W_hr, const float* __restrict__ W_hz,
    const float* __restrict__ W_hh,
    float* __restrict__ out)
{
    extern __shared__ char smem[];
    const uint32_t sb = (uint32_t)__cvta_generic_to_shared(smem);
    __shared__ int s_base;
    const int tid  = threadIdx.x;
    const int w    = tid >> 5, lane = tid & 31;
    const int g    = lane >> 2, c = lane & 3;
    const int cta  = blockIdx.x;
    const int j0   = cta * 8;

    if (tid == 0) s_base = g_phase;

    // ---- build resident B fragments (exact mma lane layout, hi/lo) ----
    // gates: ntile 0 = W_hr, ntile 1 = W_hz
#pragma unroll 1
    for (int i = 0; i < 16; i++) {
        const int nt = i >> 3;
        const int sg = (i & 7) * 8 + w;
        const float* __restrict__ W = nt ? W_hz : W_hr;
        const int col = j0 + g;
        const int k0 = sg * 16 + 2 * c;
        const float w0 = W[(size_t)k0 * H_ + col];
        const float w1 = W[(size_t)(k0 + 1) * H_ + col];
        const float w2 = W[(size_t)(k0 + 8) * H_ + col];
        const float w3 = W[(size_t)(k0 + 9) * H_ + col];
        uint32_t l0, l1;
        const uint32_t h0 = pack2(w0, w1, l0);
        const uint32_t h1 = pack2(w2, w3, l1);
        const uint32_t off = (uint32_t)(((nt << 6) + sg) * 32 + lane) * 8;
        *(uint2*)(smem + BGH + off) = make_uint2(h0, h1);
        *(uint2*)(smem + BGL + off) = make_uint2(l0, l1);
    }
#pragma unroll 1
    for (int i = 0; i < 8; i++) {
        const int sg = i * 8 + w;
        const int col = j0 + g;
        const int k0 = sg * 16 + 2 * c;
        const float w0 = W_hh[(size_t)k0 * H_ + col];
        const float w1 = W_hh[(size_t)(k0 + 1) * H_ + col];
        const float w2 = W_hh[(size_t)(k0 + 8) * H_ + col];
        const float w3 = W_hh[(size_t)(k0 + 9) * H_ + col];
        uint32_t l0, l1;
        const uint32_t h0 = pack2(w0, w1, l0);
        const uint32_t h1 = pack2(w2, w3, l1);
        const uint32_t off = (uint32_t)(sg * 32 + lane) * 8;
        *(uint2*)(smem + BCH + off) = make_uint2(h0, h1);
        *(uint2*)(smem + BCL + off) = make_uint2(l0, l1);
    }

    // ---- initial h -> bf16 hi/lo split (this CTA's 8 columns) ----
    if (tid < 64) {
#pragma unroll
        for (int jj = 0; jj < 8; jj += 2) {
            uint32_t lo;
            const uint32_t hi = pack2(state[(size_t)tid * H_ + j0 + jj],
                                      state[(size_t)tid * H_ + j0 + jj + 1], lo);
            *(uint32_t*)(g_h_bf + (size_t)tid * 2048 + j0 + jj)        = hi;
            *(uint32_t*)(g_h_bf + (size_t)tid * 2048 + 1024 + j0 + jj) = lo;
        }
    }
    __syncthreads();
    const int base = s_base;
    grid_barrier(base + 1);

    const int b1 = (w & 3) * 16 + g;
    const int b2 = b1 + 8;
    const int jj = j0 + 2 * c;

    for (int t = 0; t < T_; t++) {
        const float* __restrict__ h_in = t ? (out + (size_t)(t - 1) * BH) : state;
        const float* __restrict__ xr_t = g_xproj + (size_t)t * BH;
        const float* __restrict__ xz_t = g_xproj + TBH + (size_t)t * BH;
        const float* __restrict__ xh_t = g_xproj + 2 * TBH + (size_t)t * BH;

        // ===== phase A: R and Z gates =====
        float acc[4] = {0.f, 0.f, 0.f, 0.f};
        run_mainloop<0>(smem, sb, tid, g_h_bf, acc);

        if (w < 4) {   // R gate -> R*h split to global
            const float2 x0 = *(const float2*)(xr_t + (size_t)b1 * H_ + jj);
            const float2 x1 = *(const float2*)(xr_t + (size_t)b2 * H_ + jj);
            const float2 h0 = *(const float2*)(h_in + (size_t)b1 * H_ + jj);
            const float2 h1 = *(const float2*)(h_in + (size_t)b2 * H_ + jj);
            const float rh00 = sigf(acc[0] + x0.x) * h0.x;
            const float rh01 = sigf(acc[1] + x0.y) * h0.y;
            const float rh10 = sigf(acc[2] + x1.x) * h1.x;
            const float rh11 = sigf(acc[3] + x1.y) * h1.y;
            uint32_t lo0, lo1;
            const uint32_t hi0 = pack2(rh00, rh01, lo0);
            const uint32_t hi1 = pack2(rh10, rh11, lo1);
            *(uint32_t*)(g_rh_bf + (size_t)b1 * 2048 + jj)        = hi0;
            *(uint32_t*)(g_rh_bf + (size_t)b1 * 2048 + 1024 + jj) = lo0;
            *(uint32_t*)(g_rh_bf + (size_t)b2 * 2048 + jj)        = hi1;
            *(uint32_t*)(g_rh_bf + (size_t)b2 * 2048 + 1024 + jj) = lo1;
        } else {       // Z gate -> smem
            const float2 x0 = *(const float2*)(xz_t + (size_t)b1 * H_ + jj);
            const float2 x1 = *(const float2*)(xz_t + (size_t)b2 * H_ + jj);
            float2 z0, z1;
            z0.x = sigf(acc[0] + x0.x); z0.y = sigf(acc[1] + x0.y);
            z1.x = sigf(acc[2] + x1.x); z1.y = sigf(acc[3] + x1.y);
            *(float2*)(smem + ZB + (uint32_t)(b1 * 8 + 2 * c) * 4) = z0;
            *(float2*)(smem + ZB + (uint32_t)(b2 * 8 + 2 * c) * 4) = z1;
        }
        grid_barrier(base + 2 + 2 * t);   // g_rh_bf complete everywhere

        // ===== phase B: candidate + state update =====
        float acc2[4] = {0.f, 0.f, 0.f, 0.f};
        run_mainloop<1>(smem, sb, tid, g_rh_bf, acc2);

        if (w >= 4) {   // write split-K partials
            *(float4*)(smem + RED + (uint32_t)(((w - 4) * 32 + lane) * 16)) =
                make_float4(acc2[0], acc2[1], acc2[2], acc2[3]);
        }
        __syncthreads();
        if (w < 4) {
            const float4 p = *(const float4*)(smem + RED + (uint32_t)((w * 32 + lane) * 16));
            acc2[0] += p.x; acc2[1] += p.y; acc2[2] += p.z; acc2[3] += p.w;

            const float2 x0 = *(const float2*)(xh_t + (size_t)b1 * H_ + jj);
            const float2 x1 = *(const float2*)(xh_t + (size_t)b2 * H_ + jj);
            const float2 h0 = *(const float2*)(h_in + (size_t)b1 * H_ + jj);
            const float2 h1 = *(const float2*)(h_in + (size_t)b2 * H_ + jj);
            const float2 z0 = *(const float2*)(smem + ZB + (uint32_t)(b1 * 8 + 2 * c) * 4);
            const float2 z1 = *(const float2*)(smem + ZB + (uint32_t)(b2 * 8 + 2 * c) * 4);

            const float v00 = z0.x * h0.x + (1.f - z0.x) * tanhf(acc2[0] + x0.x);
            const float v01 = z0.y * h0.y + (1.f - z0.y) * tanhf(acc2[1] + x0.y);
            const float v10 = z1.x * h1.x + (1.f - z1.x) * tanhf(acc2[2] + x1.x);
            const float v11 = z1.y * h1.y + (1.f - z1.y) * tanhf(acc2[3] + x1.y);

            float* out_t = out + (size_t)t * BH;
            *(float2*)(out_t + (size_t)b1 * H_ + jj) = make_float2(v00, v01);
            *(float2*)(out_t + (size_t)b2 * H_ + jj) = make_float2(v10, v11);

            uint32_t lo0, lo1;
            const uint32_t hi0 = pack2(v00, v01, lo0);
            const uint32_t hi1 = pack2(v10, v11, lo1);
            *(uint32_t*)(g_h_bf + (size_t)b1 * 2048 + jj)        = hi0;
            *(uint32_t*)(g_h_bf + (size_t)b1 * 2048 + 1024 + jj) = lo0;
            *(uint32_t*)(g_h_bf + (size_t)b2 * 2048 + jj)        = hi1;
            *(uint32_t*)(g_h_bf + (size_t)b2 * 2048 + 1024 + jj) = lo1;
        }
        grid_barrier(base + 3 + 2 * t);   // out[t] + g_h_bf complete everywhere
    }
}

// ---------------- host launcher ----------------
extern "C" void kernel_launch(void* const* d_in, const int* in_sizes, int n_in,
                              void* d_out, int out_size)
{
    (void)in_sizes; (void)n_in; (void)out_size;
    const float* X     = (const float*)d_in[0];
    const float* state = (const float*)d_in[1];
    const float* W_xr  = (const float*)d_in[2];
    const float* W_hr  = (const float*)d_in[3];
    const float* b_r   = (const float*)d_in[4];
    const float* W_xz  = (const float*)d_in[5];
    const float* W_hz  = (const float*)d_in[6];
    const float* b_z   = (const float*)d_in[7];
    const float* W_xh  = (const float*)d_in[8];
    const float* W_hh  = (const float*)d_in[9];
    const float* b_h   = (const float*)d_in[10];
    float* out = (float*)d_out;

    {
        dim3 grid(H_ / 128, (T_ * B_) / 128, 3);
        proj_kernel<<<grid, 256>>>(X, W_xr, W_xz, W_xh, b_r, b_z, b_h);
    }

    static int smem_set = 0;
    if (!smem_set) {
        cudaFuncSetAttribute(scan_kernel,
                             cudaFuncAttributeMaxDynamicSharedMemorySize,
                             (int)SMEM_TOTAL);
        smem_set = 1;
    }
    scan_kernel<<<NCTA, NTHR, SMEM_TOTAL>>>(state, W_hr, W_hz, W_hh, out);

    cudaMemcpyAsync(out + TBH, out + TBH - BH, (size_t)BH * sizeof(float),
                    cudaMemcpyDeviceToDevice, 0);
}

// round 15
// speedup vs baseline: 2.2291x; 1.1836x over previous
#include <cuda_runtime.h>
#include <cuda_bf16.h>
#include <math.h>
#include <stdint.h>

// ---------------- problem constants ----------------
constexpr int T_   = 512;
constexpr int B_   = 64;
constexpr int DIN_ = 1024;
constexpr int H_   = 1024;
constexpr size_t TBH = (size_t)T_ * B_ * H_;
constexpr int BH = B_ * H_;

constexpr int NCTA = 128;
constexpr int NTHR = 256;

// ---------------- device scratch ----------------
__device__ float         g_xproj[3ULL * TBH];
__device__ __nv_bfloat16 g_h_bf[64 * 2048];    // [b][ hi(1024) | lo(1024) ]
__device__ __nv_bfloat16 g_rh_bf[64 * 2048];   // R*h split
__device__ __nv_bfloat16 g_xbf[(size_t)32768 * 2048];   // X as [row][hi|lo] bf16
__device__ uint4         g_wfrag[3 * 64 * 128 * 32];    // W_x* pre-packed mma fragments
__device__ int           g_count = 0;
__device__ volatile int  g_phase = 0;

// ---------------- scan smem layout (bytes) ----------------
constexpr uint32_t BGH   = 0;          // gates B hi:  [2][64][32]*8 = 32768
constexpr uint32_t BGL   = 32768;      // gates B lo
constexpr uint32_t BCH   = 65536;      // cand  B hi:  [64][32]*8    = 16384
constexpr uint32_t BCL   = 81920;      // cand  B lo
constexpr uint32_t AB0   = 98304;      // A ring (3 buffers)
constexpr uint32_t ABSTR = 34816;      // per-buffer stride (hi 17408 + lo 17408)
constexpr uint32_t AHALF = 17408;      // lo offset inside a buffer
constexpr uint32_t ZB    = 202752;     // Z gate values: 64*8*4 = 2048
constexpr uint32_t RED   = 204800;     // phase-B split-K partials: 2048
constexpr uint32_t SMEM_TOTAL = 206848;
constexpr int APITCH = 136;            // staged A row pitch (bf16 elems)

// ---------------- proj smem layout ----------------
constexpr uint32_t P_ABUF  = 20480;    // per A buffer (hi 10240 + lo 10240)
constexpr uint32_t P_AHALF = 10240;
constexpr uint32_t P_BBASE = 61440;    // 3 A buffers before this
constexpr uint32_t P_BBUF  = 16384;
constexpr uint32_t P_SMEM  = 110592;   // 3*20480 + 3*16384
constexpr int P_APITCH = 40;           // bf16 elems per row (80B, odd 16B units)

// ---------------- helpers ----------------
__device__ __forceinline__ float sigf(float x) { return 1.f / (1.f + __expf(-x)); }

__device__ __forceinline__ uint32_t pack2(float a, float b, uint32_t& lo) {
    __nv_bfloat16 ah = __float2bfloat16(a), bh = __float2bfloat16(b);
    __nv_bfloat16 al = __float2bfloat16(a - __bfloat162float(ah));
    __nv_bfloat16 bl = __float2bfloat16(b - __bfloat162float(bh));
    lo = (uint32_t)__bfloat16_as_ushort(al) | ((uint32_t)__bfloat16_as_ushort(bl) << 16);
    return (uint32_t)__bfloat16_as_ushort(ah) | ((uint32_t)__bfloat16_as_ushort(bh) << 16);
}

__device__ __forceinline__ void mma_bf16(float* d, const uint32_t* a, const uint2& b) {
    asm volatile(
        "mma.sync.aligned.m16n8k16.row.col.f32.bf16.bf16.f32 "
        "{%0,%1,%2,%3}, {%4,%5,%6,%7}, {%8,%9}, {%0,%1,%2,%3};"
        : "+f"(d[0]), "+f"(d[1]), "+f"(d[2]), "+f"(d[3])
        : "r"(a[0]), "r"(a[1]), "r"(a[2]), "r"(a[3]), "r"(b.x), "r"(b.y));
}

__device__ __forceinline__ void cp16(uint32_t saddr, const void* gptr) {
    asm volatile("cp.async.cg.shared.global [%0], [%1], 16;" :: "r"(saddr), "l"(gptr));
}

// ---------------- convert X -> bf16 hi/lo ----------------
__global__ __launch_bounds__(256) void conv_x_kernel(const float* __restrict__ X)
{
    const size_t idx = (size_t)blockIdx.x * 256 + threadIdx.x;   // 32768*512 total
    const int row = (int)(idx >> 9);
    const int col = ((int)idx & 511) * 2;
    float2 v = *(const float2*)(X + (size_t)row * 1024 + col);
    uint32_t lo;
    const uint32_t hi = pack2(v.x, v.y, lo);
    *(uint32_t*)(g_xbf + (size_t)row * 2048 + col)        = hi;
    *(uint32_t*)(g_xbf + (size_t)row * 2048 + 1024 + col) = lo;
}

// ---------------- pack W_x* into mma B-fragment layout ----------------
// frag[mat][sg][nt][lane] = uint4(hi0, hi1, lo0, lo1); sg = kstep (k16), nt = n8 tile
__global__ __launch_bounds__(256) void pack_w_kernel(
    const float* __restrict__ Wr, const float* __restrict__ Wz, const float* __restrict__ Wh)
{
    const int idx = blockIdx.x * 256 + threadIdx.x;   // 3*64*128*32 = 786432
    const int lane = idx & 31;
    const int nt = (idx >> 5) & 127;
    const int sg = (idx >> 12) & 63;
    const int mat = idx >> 18;
    const float* __restrict__ W = (mat == 0) ? Wr : ((mat == 1) ? Wz : Wh);
    const int c = lane & 3, g = lane >> 2;
    const int k0 = sg * 16 + 2 * c;
    const int col = nt * 8 + g;
    const float w0 = W[(size_t)k0 * H_ + col];
    const float w1 = W[(size_t)(k0 + 1) * H_ + col];
    const float w2 = W[(size_t)(k0 + 8) * H_ + col];
    const float w3 = W[(size_t)(k0 + 9) * H_ + col];
    uint32_t l0, l1;
    const uint32_t h0 = pack2(w0, w1, l0);
    const uint32_t h1 = pack2(w2, w3, l1);
    g_wfrag[idx] = make_uint4(h0, h1, l0, l1);
}

// ---------------- Phase 1: input projections via HMMA (3-term bf16 split) ----------------
__global__ __launch_bounds__(256, 2) void proj_mma_kernel(
    const float* __restrict__ b0, const float* __restrict__ b1, const float* __restrict__ b2)
{
    extern __shared__ char sm[];
    const uint32_t sb = (uint32_t)__cvta_generic_to_shared(sm);
    const int tid = threadIdx.x;
    const int w = tid >> 5, lane = tid & 31;
    const int g = lane >> 2, c = lane & 3;
    const int wm = w >> 1, wn = w & 1;
    const int mat = blockIdx.z;
    const int n0 = blockIdx.x * 128;
    const int m0 = blockIdx.y * 128;
    const float* __restrict__ bias = (mat == 0) ? b0 : ((mat == 1) ? b1 : b2);

    const int ab = tid >> 1, aq = tid & 1;   // A staging: row, col-half
    const int bs = tid >> 7, bt = tid & 127; // B staging: sg half, 64B unit

    auto stage = [&](int kc, int buf) {
        {   // A: X tile [128 x 32] hi+lo
            const __nv_bfloat16* gp = g_xbf + (size_t)(m0 + ab) * 2048 + kc * 32 + aq * 16;
            uint32_t ad = sb + (uint32_t)buf * P_ABUF + (uint32_t)((ab * P_APITCH + aq * 16) * 2);
            cp16(ad, gp);
            cp16(ad + 16, gp + 8);
            cp16(ad + P_AHALF, gp + 1024);
            cp16(ad + P_AHALF + 16, gp + 1024 + 8);
        }
        {   // B: frag blocks for sg = kc*2 + bs, nt in [n0/8, n0/8+16)
            const char* gp = (const char*)(g_wfrag +
                ((size_t)(mat * 64 + kc * 2 + bs) * 128 + (n0 >> 3)) * 32) + bt * 64;
            uint32_t ad = sb + P_BBASE + (uint32_t)buf * P_BBUF + (uint32_t)(bs * 8192 + bt * 64);
            cp16(ad, gp); cp16(ad + 16, gp + 16); cp16(ad + 32, gp + 32); cp16(ad + 48, gp + 48);
        }
        asm volatile("cp.async.commit_group;");
    };

    float acc[2][8][4];
#pragma unroll
    for (int mt = 0; mt < 2; mt++)
#pragma unroll
        for (int j = 0; j < 8; j++)
#pragma unroll
            for (int i = 0; i < 4; i++) acc[mt][j][i] = 0.f;

    stage(0, 0); stage(1, 1);
    int buf = 0, sbuf = 2;
    for (int kc = 0; kc < 32; kc++) {
        if (kc < 31) asm volatile("cp.async.wait_group 1;");
        else         asm volatile("cp.async.wait_group 0;");
        __syncthreads();
        if (kc + 2 < 32) stage(kc + 2, sbuf);

        const char* A  = sm + (uint32_t)buf * P_ABUF;
        const char* Bp = sm + P_BBASE + (uint32_t)buf * P_BBUF;
#pragma unroll
        for (int s = 0; s < 2; s++) {
            uint4 bf[8];
#pragma unroll
            for (int j = 0; j < 8; j++)
                bf[j] = *(const uint4*)(Bp + s * 8192 + (uint32_t)(((wn * 8 + j) * 32 + lane) * 16));
#pragma unroll
            for (int mt = 0; mt < 2; mt++) {
                const char* ap = A + (size_t)((wm * 32 + mt * 16 + g) * P_APITCH + s * 16 + 2 * c) * 2;
                uint32_t ah[4], al[4];
                ah[0] = *(const uint32_t*)ap;
                ah[1] = *(const uint32_t*)(ap + P_APITCH * 16);
                ah[2] = *(const uint32_t*)(ap + 16);
                ah[3] = *(const uint32_t*)(ap + P_APITCH * 16 + 16);
                const char* alp = ap + P_AHALF;
                al[0] = *(const uint32_t*)alp;
                al[1] = *(const uint32_t*)(alp + P_APITCH * 16);
                al[2] = *(const uint32_t*)(alp + 16);
                al[3] = *(const uint32_t*)(alp + P_APITCH * 16 + 16);
#pragma unroll
                for (int j = 0; j < 8; j++) {
                    const uint2 bh = make_uint2(bf[j].x, bf[j].y);
                    const uint2 bl = make_uint2(bf[j].z, bf[j].w);
                    mma_bf16(acc[mt][j], ah, bh);
                    mma_bf16(acc[mt][j], ah, bl);
                    mma_bf16(acc[mt][j], al, bh);
                }
            }
        }
        buf  = (buf  == 2) ? 0 : buf + 1;
        sbuf = (sbuf == 2) ? 0 : sbuf + 1;
    }

    float* __restrict__ C = g_xproj + (size_t)mat * TBH;
#pragma unroll
    for (int mt = 0; mt < 2; mt++) {
#pragma unroll
        for (int j = 0; j < 8; j++) {
            const int col = n0 + wn * 64 + j * 8 + 2 * c;
            const int r0  = m0 + wm * 32 + mt * 16 + g;
            const float2 bb = *(const float2*)(bias + col);
            *(float2*)(C + (size_t)r0 * H_ + col) =
                make_float2(acc[mt][j][0] + bb.x, acc[mt][j][1] + bb.y);
            *(float2*)(C + (size_t)(r0 + 8) * H_ + col) =
                make_float2(acc[mt][j][2] + bb.x, acc[mt][j][3] + bb.y);
        }
    }
}

// ---------------- grid barrier (busy poll) ----------------
__device__ __forceinline__ void grid_barrier(int target)
{
    __threadfence();
    __syncthreads();
    if (threadIdx.x == 0) {
        int prev = atomicAdd(&g_count, 1);
        if (prev == NCTA - 1) {
            g_count = 0;
            __threadfence();
            g_phase = target;
        } else {
            while (g_phase < target) { }
        }
    }
    __syncthreads();
}

// ---------------- streamed HMMA mainloop (ring-3, prefetch distance 2) ----------------
template<int PHASE>
__device__ __forceinline__ void run_mainloop(char* sm, uint32_t sb, int tid,
                                             const __nv_bfloat16* __restrict__ src,
                                             float* acc)
{
    const int w = tid >> 5, lane = tid & 31;
    const int g = lane >> 2, c = lane & 3;
    const int m = w & 3;
    const int sel = w >> 2;
    const int arow = m * 16 + g;
    const int b = tid >> 2, q = tid & 3;   // staging role

    auto stage = [&](int chunk, int bufi) {
        const __nv_bfloat16* gp = src + (size_t)b * 2048 + chunk * 128 + q * 32;
        uint32_t ad = sb + AB0 + (uint32_t)bufi * ABSTR + (uint32_t)((b * APITCH + q * 32) * 2);
#pragma unroll
        for (int u = 0; u < 4; u++) {
            cp16(ad + u * 16, gp + u * 8);
            cp16(ad + AHALF + u * 16, gp + 1024 + u * 8);
        }
        asm volatile("cp.async.commit_group;");
    };

    stage(0, 0); stage(1, 1);
    int buf = 0, sbuf = 2;
    for (int chunk = 0; chunk < 8; chunk++) {
        if (chunk < 7) asm volatile("cp.async.wait_group 1;");
        else           asm volatile("cp.async.wait_group 0;");
        __syncthreads();
        if (chunk + 2 < 8) stage(chunk + 2, sbuf);

        const bool active = (PHASE == 0) ? true : ((chunk & 1) == sel);
        if (active) {
            const char* AH = sm + AB0 + (uint32_t)buf * ABSTR;
            const uint32_t bb_hi = (PHASE == 0) ? (BGH + (uint32_t)sel * 16384u) : BCH;
            const uint32_t bb_lo = (PHASE == 0) ? (BGL + (uint32_t)sel * 16384u) : BCL;
#pragma unroll
            for (int s = 0; s < 8; s++) {
                const int sg = chunk * 8 + s;
                const char* ap = AH + (size_t)(arow * APITCH + s * 16 + 2 * c) * 2;
                uint32_t ah[4], al[4];
                ah[0] = *(const uint32_t*)ap;
                ah[1] = *(const uint32_t*)(ap + APITCH * 16);
                ah[2] = *(const uint32_t*)(ap + 16);
                ah[3] = *(const uint32_t*)(ap + APITCH * 16 + 16);
                const char* alp = ap + AHALF;
                al[0] = *(const uint32_t*)alp;
                al[1] = *(const uint32_t*)(alp + APITCH * 16);
                al[2] = *(const uint32_t*)(alp + 16);
                al[3] = *(const uint32_t*)(alp + APITCH * 16 + 16);
                uint2 bh = *(const uint2*)(sm + bb_hi + (size_t)(sg * 32 + lane) * 8);
                uint2 bl = *(const uint2*)(sm + bb_lo + (size_t)(sg * 32 + lane) * 8);
                mma_bf16(acc, ah, bh);
                mma_bf16(acc, ah, bl);
                mma_bf16(acc, al, bh);
            }
        }
        buf  = (buf  == 2) ? 0 : buf + 1;
        sbuf = (sbuf == 2) ? 0 : sbuf + 1;
    }
}

// ---------------- Phase 2: persistent HMMA scan ----------------
__global__ __launch_bounds__(NTHR, 1) void scan_kernel(
    const float* __restrict__ state,
    const float* __restrict__ W_hr, const float* __restrict__ W_hz,
    const float* __restrict__ W_hh,
    float* __restrict__ out)
{
    extern __shared__ char smem[];
    const uint32_t sb = (uint32_t)__cvta_generic_to_shared(smem);
    __shared__ int s_base;
    const int tid  = threadIdx.x;
    const int w    = tid >> 5, lane = tid & 31;
    const int g    = lane >> 2, c = lane & 3;
    const int cta  = blockIdx.x;
    const int j0   = cta * 8;

    if (tid == 0) s_base = g_phase;

    // ---- build resident B fragments (proven layout) ----
#pragma unroll 1
    for (int i = 0; i < 16; i++) {
        const int nt = i >> 3;
        const int sg = (i & 7) * 8 + w;
        const float* __restrict__ W = nt ? W_hz : W_hr;
        const int col = j0 + g;
        const int k0 = sg * 16 + 2 * c;
        const float w0 = W[(size_t)k0 * H_ + col];
        const float w1 = W[(size_t)(k0 + 1) * H_ + col];
        const float w2 = W[(size_t)(k0 + 8) * H_ + col];
        const float w3 = W[(size_t)(k0 + 9) * H_ + col];
        uint32_t l0, l1;
        const uint32_t h0 = pack2(w0, w1, l0);
        const uint32_t h1 = pack2(w2, w3, l1);
        const uint32_t off = (uint32_t)(((nt << 6) + sg) * 32 + lane) * 8;
        *(uint2*)(smem + BGH + off) = make_uint2(h0, h1);
        *(uint2*)(smem + BGL + off) = make_uint2(l0, l1);
    }
#pragma unroll 1
    for (int i = 0; i < 8; i++) {
        const int sg = i * 8 + w;
        const int col = j0 + g;
        const int k0 = sg * 16 + 2 * c;
        const float w0 = W_hh[(size_t)k0 * H_ + col];
        const float w1 = W_hh[(size_t)(k0 + 1) * H_ + col];
        const float w2 = W_hh[(size_t)(k0 + 8) * H_ + col];
        const float w3 = W_hh[(size_t)(k0 + 9) * H_ + col];
        uint32_t l0, l1;
        const uint32_t h0 = pack2(w0, w1, l0);
        const uint32_t h1 = pack2(w2, w3, l1);
        const uint32_t off = (uint32_t)(sg * 32 + lane) * 8;
        *(uint2*)(smem + BCH + off) = make_uint2(h0, h1);
        *(uint2*)(smem + BCL + off) = make_uint2(l0, l1);
    }

    // ---- initial h -> bf16 hi/lo split (this CTA's 8 columns) ----
    if (tid < 64) {
#pragma unroll
        for (int jj = 0; jj < 8; jj += 2) {
            uint32_t lo;
            const uint32_t hi = pack2(state[(size_t)tid * H_ + j0 + jj],
                                      state[(size_t)tid * H_ + j0 + jj + 1], lo);
            *(uint32_t*)(g_h_bf + (size_t)tid * 2048 + j0 + jj)        = hi;
            *(uint32_t*)(g_h_bf + (size_t)tid * 2048 + 1024 + j0 + jj) = lo;
        }
    }
    __syncthreads();
    const int base = s_base;
    grid_barrier(base + 1);

    const int b1 = (w & 3) * 16 + g;
    const int b2 = b1 + 8;
    const int jj = j0 + 2 * c;

    for (int t = 0; t < T_; t++) {
        const float* __restrict__ h_in = t ? (out + (size_t)(t - 1) * BH) : state;
        const float* __restrict__ xr_t = g_xproj + (size_t)t * BH;
        const float* __restrict__ xz_t = g_xproj + TBH + (size_t)t * BH;
        const float* __restrict__ xh_t = g_xproj + 2 * TBH + (size_t)t * BH;

        // ===== phase A: R and Z gates =====
        float acc[4] = {0.f, 0.f, 0.f, 0.f};
        run_mainloop<0>(smem, sb, tid, g_h_bf, acc);

        if (w < 4) {   // R gate -> R*h split to global
            const float2 x0 = *(const float2*)(xr_t + (size_t)b1 * H_ + jj);
            const float2 x1 = *(const float2*)(xr_t + (size_t)b2 * H_ + jj);
            const float2 h0 = *(const float2*)(h_in + (size_t)b1 * H_ + jj);
            const float2 h1 = *(const float2*)(h_in + (size_t)b2 * H_ + jj);
            const float rh00 = sigf(acc[0] + x0.x) * h0.x;
            const float rh01 = sigf(acc[1] + x0.y) * h0.y;
            const float rh10 = sigf(acc[2] + x1.x) * h1.x;
            const float rh11 = sigf(acc[3] + x1.y) * h1.y;
            uint32_t lo0, lo1;
            const uint32_t hi0 = pack2(rh00, rh01, lo0);
            const uint32_t hi1 = pack2(rh10, rh11, lo1);
            *(uint32_t*)(g_rh_bf + (size_t)b1 * 2048 + jj)        = hi0;
            *(uint32_t*)(g_rh_bf + (size_t)b1 * 2048 + 1024 + jj) = lo0;
            *(uint32_t*)(g_rh_bf + (size_t)b2 * 2048 + jj)        = hi1;
            *(uint32_t*)(g_rh_bf + (size_t)b2 * 2048 + 1024 + jj) = lo1;
        } else {       // Z gate -> smem
            const float2 x0 = *(const float2*)(xz_t + (size_t)b1 * H_ + jj);
            const float2 x1 = *(const float2*)(xz_t + (size_t)b2 * H_ + jj);
            float2 z0, z1;
            z0.x = sigf(acc[0] + x0.x); z0.y = sigf(acc[1] + x0.y);
            z1.x = sigf(acc[2] + x1.x); z1.y = sigf(acc[3] + x1.y);
            *(float2*)(smem + ZB + (uint32_t)(b1 * 8 + 2 * c) * 4) = z0;
            *(float2*)(smem + ZB + (uint32_t)(b2 * 8 + 2 * c) * 4) = z1;
        }
        grid_barrier(base + 2 + 2 * t);   // g_rh_bf complete everywhere

        // ===== phase B: candidate + state update =====
        float acc2[4] = {0.f, 0.f, 0.f, 0.f};
        run_mainloop<1>(smem, sb, tid, g_rh_bf, acc2);

        if (w >= 4) {   // write split-K partials
            *(float4*)(smem + RED + (uint32_t)(((w - 4) * 32 + lane) * 16)) =
                make_float4(acc2[0], acc2[1], acc2[2], acc2[3]);
        }
        __syncthreads();
        if (w < 4) {
            const float4 p = *(const float4*)(smem + RED + (uint32_t)((w * 32 + lane) * 16));
            acc2[0] += p.x; acc2[1] += p.y; acc2[2] += p.z; acc2[3] += p.w;

            const float2 x0 = *(const float2*)(xh_t + (size_t)b1 * H_ + jj);
            const float2 x1 = *(const float2*)(xh_t + (size_t)b2 * H_ + jj);
            const float2 h0 = *(const float2*)(h_in + (size_t)b1 * H_ + jj);
            const float2 h1 = *(const float2*)(h_in + (size_t)b2 * H_ + jj);
            const float2 z0 = *(const float2*)(smem + ZB + (uint32_t)(b1 * 8 + 2 * c) * 4);
            const float2 z1 = *(const float2*)(smem + ZB + (uint32_t)(b2 * 8 + 2 * c) * 4);

            const float v00 = z0.x * h0.x + (1.f - z0.x) * tanhf(acc2[0] + x0.x);
            const float v01 = z0.y * h0.y + (1.f - z0.y) * tanhf(acc2[1] + x0.y);
            const float v10 = z1.x * h1.x + (1.f - z1.x) * tanhf(acc2[2] + x1.x);
            const float v11 = z1.y * h1.y + (1.f - z1.y) * tanhf(acc2[3] + x1.y);

            float* out_t = out + (size_t)t * BH;
            *(float2*)(out_t + (size_t)b1 * H_ + jj) = make_float2(v00, v01);
            *(float2*)(out_t + (size_t)b2 * H_ + jj) = make_float2(v10, v11);

            uint32_t lo0, lo1;
            const uint32_t hi0 = pack2(v00, v01, lo0);
            const uint32_t hi1 = pack2(v10, v11, lo1);
            *(uint32_t*)(g_h_bf + (size_t)b1 * 2048 + jj)        = hi0;
            *(uint32_t*)(g_h_bf + (size_t)b1 * 2048 + 1024 + jj) = lo0;
            *(uint32_t*)(g_h_bf + (size_t)b2 * 2048 + jj)        = hi1;
            *(uint32_t*)(g_h_bf + (size_t)b2 * 2048 + 1024 + jj) = lo1;
        }
        grid_barrier(base + 3 + 2 * t);   // out[t] + g_h_bf complete everywhere
    }
}

// ---------------- host launcher ----------------
extern "C" void kernel_launch(void* const* d_in, const int* in_sizes, int n_in,
                              void* d_out, int out_size)
{
    (void)in_sizes; (void)n_in; (void)out_size;
    const float* X     = (const float*)d_in[0];
    const float* state = (const float*)d_in[1];
    const float* W_xr  = (const float*)d_in[2];
    const float* W_hr  = (const float*)d_in[3];
    const float* b_r   = (const float*)d_in[4];
    const float* W_xz  = (const float*)d_in[5];
    const float* W_hz  = (const float*)d_in[6];
    const float* b_z   = (const float*)d_in[7];
    const float* W_xh  = (const float*)d_in[8];
    const float* W_hh  = (const float*)d_in[9];
    const float* b_h   = (const float*)d_in[10];
    float* out = (float*)d_out;

    static int attr_set = 0;
    if (!attr_set) {
        cudaFuncSetAttribute(proj_mma_kernel,
                             cudaFuncAttributeMaxDynamicSharedMemorySize, (int)P_SMEM);
        cudaFuncSetAttribute(scan_kernel,
                             cudaFuncAttributeMaxDynamicSharedMemorySize, (int)SMEM_TOTAL);
        attr_set = 1;
    }

    // Phase 1: converts + HMMA projections
    conv_x_kernel<<<65536, 256>>>(X);
    pack_w_kernel<<<3072, 256>>>(W_xr, W_xz, W_xh);
    {
        dim3 grid(H_ / 128, (T_ * B_) / 128, 3);
        proj_mma_kernel<<<grid, 256, P_SMEM>>>(b_r, b_z, b_h);
    }

    // Phase 2: persistent scan
    scan_kernel<<<NCTA, NTHR, SMEM_TOTAL>>>(state, W_hr, W_hz, W_hh, out);

    // final_state = outputs[T-1]
    cudaMemcpyAsync(out + TBH, out + TBH - BH, (size_t)BH * sizeof(float),
                    cudaMemcpyDeviceToDevice, 0);
}

// round 16
// speedup vs baseline: 3.5067x; 1.5731x over previous
#include <cuda_runtime.h>
#include <cuda_bf16.h>
#include <math.h>
#include <stdint.h>

// ---------------- problem constants ----------------
constexpr int T_   = 512;
constexpr int B_   = 64;
constexpr int DIN_ = 1024;
constexpr int H_   = 1024;
constexpr size_t TBH = (size_t)T_ * B_ * H_;
constexpr int BH = B_ * H_;

constexpr int NCTA = 128;
constexpr int NTHR = 256;

// ---------------- device scratch ----------------
__device__ float         g_xproj[3ULL * TBH];
__device__ __nv_bfloat16 g_xbf[(size_t)32768 * 2048];   // X as [row][hi|lo] bf16
__device__ uint4         g_wfrag[3 * 64 * 128 * 32];    // W_x* pre-packed mma fragments
// h and R*h in mma A-fragment layout: [mt(4)][sg(64)][lane(32)] -> uint4 (4 frag regs)
__device__ uint4         g_hf_hi[4 * 64 * 32];
__device__ uint4         g_hf_lo[4 * 64 * 32];
__device__ uint4         g_rf_hi[4 * 64 * 32];
__device__ uint4         g_rf_lo[4 * 64 * 32];
__device__ int           g_count = 0;
__device__ volatile int  g_phase = 0;

// ---------------- scan smem layout (bytes) ----------------
// B fragments as uint4 (hi0,hi1,lo0,lo1) per [tile][sg][lane]
constexpr uint32_t BG   = 0;        // gates: [2][64][32]*16 = 65536
constexpr uint32_t BC   = 65536;    // cand:  [64][32]*16    = 32768
constexpr uint32_t ZB   = 98304;    // Z gate values: 2048
constexpr uint32_t RED  = 100352;   // phase-B split-K partials: 2048
constexpr uint32_t SMEM_TOTAL = 102400;

// ---------------- proj smem layout ----------------
constexpr uint32_t P_ABUF  = 20480;
constexpr uint32_t P_AHALF = 10240;
constexpr uint32_t P_BBASE = 61440;
constexpr uint32_t P_BBUF  = 16384;
constexpr uint32_t P_SMEM  = 110592;
constexpr int P_APITCH = 40;

// ---------------- helpers ----------------
__device__ __forceinline__ float sigf(float x) { return 1.f / (1.f + __expf(-x)); }

__device__ __forceinline__ uint32_t pack2(float a, float b, uint32_t& lo) {
    __nv_bfloat16 ah = __float2bfloat16(a), bh = __float2bfloat16(b);
    __nv_bfloat16 al = __float2bfloat16(a - __bfloat162float(ah));
    __nv_bfloat16 bl = __float2bfloat16(b - __bfloat162float(bh));
    lo = (uint32_t)__bfloat16_as_ushort(al) | ((uint32_t)__bfloat16_as_ushort(bl) << 16);
    return (uint32_t)__bfloat16_as_ushort(ah) | ((uint32_t)__bfloat16_as_ushort(bh) << 16);
}

__device__ __forceinline__ void mma_bf16(float* d, const uint32_t* a, const uint2& b) {
    asm volatile(
        "mma.sync.aligned.m16n8k16.row.col.f32.bf16.bf16.f32 "
        "{%0,%1,%2,%3}, {%4,%5,%6,%7}, {%8,%9}, {%0,%1,%2,%3};"
        : "+f"(d[0]), "+f"(d[1]), "+f"(d[2]), "+f"(d[3])
        : "r"(a[0]), "r"(a[1]), "r"(a[2]), "r"(a[3]), "r"(b.x), "r"(b.y));
}

__device__ __forceinline__ void cp16(uint32_t saddr, const void* gptr) {
    asm volatile("cp.async.cg.shared.global [%0], [%1], 16;" :: "r"(saddr), "l"(gptr));
}

// L2-only vector load (L1 bypass — mandatory for cross-SM reuse inside a persistent kernel)
__device__ __forceinline__ uint4 ldg_cg4(const uint4* p) {
    uint4 v;
    asm volatile("ld.global.cg.v4.u32 {%0,%1,%2,%3}, [%4];"
                 : "=r"(v.x), "=r"(v.y), "=r"(v.z), "=r"(v.w) : "l"(p));
    return v;
}

// ---------------- convert X -> bf16 hi/lo ----------------
__global__ __launch_bounds__(256) void conv_x_kernel(const float* __restrict__ X)
{
    const size_t idx = (size_t)blockIdx.x * 256 + threadIdx.x;
    const int row = (int)(idx >> 9);
    const int col = ((int)idx & 511) * 2;
    float2 v = *(const float2*)(X + (size_t)row * 1024 + col);
    uint32_t lo;
    const uint32_t hi = pack2(v.x, v.y, lo);
    *(uint32_t*)(g_xbf + (size_t)row * 2048 + col)        = hi;
    *(uint32_t*)(g_xbf + (size_t)row * 2048 + 1024 + col) = lo;
}

// ---------------- pack W_x* into mma B-fragment layout ----------------
__global__ __launch_bounds__(256) void pack_w_kernel(
    const float* __restrict__ Wr, const float* __restrict__ Wz, const float* __restrict__ Wh)
{
    const int idx = blockIdx.x * 256 + threadIdx.x;
    const int lane = idx & 31;
    const int nt = (idx >> 5) & 127;
    const int sg = (idx >> 12) & 63;
    const int mat = idx >> 18;
    const float* __restrict__ W = (mat == 0) ? Wr : ((mat == 1) ? Wz : Wh);
    const int c = lane & 3, g = lane >> 2;
    const int k0 = sg * 16 + 2 * c;
    const int col = nt * 8 + g;
    const float w0 = W[(size_t)k0 * H_ + col];
    const float w1 = W[(size_t)(k0 + 1) * H_ + col];
    const float w2 = W[(size_t)(k0 + 8) * H_ + col];
    const float w3 = W[(size_t)(k0 + 9) * H_ + col];
    uint32_t l0, l1;
    const uint32_t h0 = pack2(w0, w1, l0);
    const uint32_t h1 = pack2(w2, w3, l1);
    g_wfrag[idx] = make_uint4(h0, h1, l0, l1);
}

// ---------------- Phase 1: input projections via HMMA (proven) ----------------
__global__ __launch_bounds__(256, 2) void proj_mma_kernel(
    const float* __restrict__ b0, const float* __restrict__ b1, const float* __restrict__ b2)
{
    extern __shared__ char sm[];
    const uint32_t sb = (uint32_t)__cvta_generic_to_shared(sm);
    const int tid = threadIdx.x;
    const int w = tid >> 5, lane = tid & 31;
    const int g = lane >> 2, c = lane & 3;
    const int wm = w >> 1, wn = w & 1;
    const int mat = blockIdx.z;
    const int n0 = blockIdx.x * 128;
    const int m0 = blockIdx.y * 128;
    const float* __restrict__ bias = (mat == 0) ? b0 : ((mat == 1) ? b1 : b2);

    const int ab = tid >> 1, aq = tid & 1;
    const int bs = tid >> 7, bt = tid & 127;

    auto stage = [&](int kc, int buf) {
        {
            const __nv_bfloat16* gp = g_xbf + (size_t)(m0 + ab) * 2048 + kc * 32 + aq * 16;
            uint32_t ad = sb + (uint32_t)buf * P_ABUF + (uint32_t)((ab * P_APITCH + aq * 16) * 2);
            cp16(ad, gp);
            cp16(ad + 16, gp + 8);
            cp16(ad + P_AHALF, gp + 1024);
            cp16(ad + P_AHALF + 16, gp + 1024 + 8);
        }
        {
            const char* gp = (const char*)(g_wfrag +
                ((size_t)(mat * 64 + kc * 2 + bs) * 128 + (n0 >> 3)) * 32) + bt * 64;
            uint32_t ad = sb + P_BBASE + (uint32_t)buf * P_BBUF + (uint32_t)(bs * 8192 + bt * 64);
            cp16(ad, gp); cp16(ad + 16, gp + 16); cp16(ad + 32, gp + 32); cp16(ad + 48, gp + 48);
        }
        asm volatile("cp.async.commit_group;");
    };

    float acc[2][8][4];
#pragma unroll
    for (int mt = 0; mt < 2; mt++)
#pragma unroll
        for (int j = 0; j < 8; j++)
#pragma unroll
            for (int i = 0; i < 4; i++) acc[mt][j][i] = 0.f;

    stage(0, 0); stage(1, 1);
    int buf = 0, sbuf = 2;
    for (int kc = 0; kc < 32; kc++) {
        if (kc < 31) asm volatile("cp.async.wait_group 1;");
        else         asm volatile("cp.async.wait_group 0;");
        __syncthreads();
        if (kc + 2 < 32) stage(kc + 2, sbuf);

        const char* A  = sm + (uint32_t)buf * P_ABUF;
        const char* Bp = sm + P_BBASE + (uint32_t)buf * P_BBUF;
#pragma unroll
        for (int s = 0; s < 2; s++) {
            uint4 bf[8];
#pragma unroll
            for (int j = 0; j < 8; j++)
                bf[j] = *(const uint4*)(Bp + s * 8192 + (uint32_t)(((wn * 8 + j) * 32 + lane) * 16));
#pragma unroll
            for (int mt = 0; mt < 2; mt++) {
                const char* ap = A + (size_t)((wm * 32 + mt * 16 + g) * P_APITCH + s * 16 + 2 * c) * 2;
                uint32_t ah[4], al[4];
                ah[0] = *(const uint32_t*)ap;
                ah[1] = *(const uint32_t*)(ap + P_APITCH * 16);
                ah[2] = *(const uint32_t*)(ap + 16);
                ah[3] = *(const uint32_t*)(ap + P_APITCH * 16 + 16);
                const char* alp = ap + P_AHALF;
                al[0] = *(const uint32_t*)alp;
                al[1] = *(const uint32_t*)(alp + P_APITCH * 16);
                al[2] = *(const uint32_t*)(alp + 16);
                al[3] = *(const uint32_t*)(alp + P_APITCH * 16 + 16);
#pragma unroll
                for (int j = 0; j < 8; j++) {
                    const uint2 bh = make_uint2(bf[j].x, bf[j].y);
                    const uint2 bl = make_uint2(bf[j].z, bf[j].w);
                    mma_bf16(acc[mt][j], ah, bh);
                    mma_bf16(acc[mt][j], ah, bl);
                    mma_bf16(acc[mt][j], al, bh);
                }
            }
        }
        buf  = (buf  == 2) ? 0 : buf + 1;
        sbuf = (sbuf == 2) ? 0 : sbuf + 1;
    }

    float* __restrict__ C = g_xproj + (size_t)mat * TBH;
#pragma unroll
    for (int mt = 0; mt < 2; mt++) {
#pragma unroll
        for (int j = 0; j < 8; j++) {
            const int col = n0 + wn * 64 + j * 8 + 2 * c;
            const int r0  = m0 + wm * 32 + mt * 16 + g;
            const float2 bb = *(const float2*)(bias + col);
            *(float2*)(C + (size_t)r0 * H_ + col) =
                make_float2(acc[mt][j][0] + bb.x, acc[mt][j][1] + bb.y);
            *(float2*)(C + (size_t)(r0 + 8) * H_ + col) =
                make_float2(acc[mt][j][2] + bb.x, acc[mt][j][3] + bb.y);
        }
    }
}

// ---------------- grid barrier (proven) ----------------
__device__ __forceinline__ void grid_barrier(int target)
{
    __threadfence();
    __syncthreads();
    if (threadIdx.x == 0) {
        int prev = atomicAdd(&g_count, 1);
        if (prev == NCTA - 1) {
            g_count = 0;
            __threadfence();
            g_phase = target;
        } else {
            while (g_phase < target) { }
        }
    }
    __syncthreads();
}

// ---------------- register-streamed HMMA mainloop ----------------
// A frags streamed L2->reg via ld.global.cg, depth-8 pipeline; B frags from smem.
template<int NSG>
__device__ __forceinline__ void mm_run(float* acc,
    const uint4* __restrict__ fh, const uint4* __restrict__ fl,
    const char* __restrict__ bp, int lane)
{
    uint4 AH[8], AL[8];
#pragma unroll
    for (int i = 0; i < 8; i++) { AH[i] = ldg_cg4(fh + i * 32); AL[i] = ldg_cg4(fl + i * 32); }
#pragma unroll 8
    for (int sg = 0; sg < NSG - 8; sg++) {
        const int sl = sg & 7;
        uint4 bf = *(const uint4*)(bp + (size_t)sg * 512 + lane * 16);
        const uint2 bh = make_uint2(bf.x, bf.y), bl = make_uint2(bf.z, bf.w);
        mma_bf16(acc, (const uint32_t*)&AH[sl], bh);
        mma_bf16(acc, (const uint32_t*)&AH[sl], bl);
        mma_bf16(acc, (const uint32_t*)&AL[sl], bh);
        AH[sl] = ldg_cg4(fh + (sg + 8) * 32);
        AL[sl] = ldg_cg4(fl + (sg + 8) * 32);
    }
#pragma unroll
    for (int sg = NSG - 8; sg < NSG; sg++) {
        const int sl = sg & 7;
        uint4 bf = *(const uint4*)(bp + (size_t)sg * 512 + lane * 16);
        const uint2 bh = make_uint2(bf.x, bf.y), bl = make_uint2(bf.z, bf.w);
        mma_bf16(acc, (const uint32_t*)&AH[sl], bh);
        mma_bf16(acc, (const uint32_t*)&AH[sl], bl);
        mma_bf16(acc, (const uint32_t*)&AL[sl], bh);
    }
}

// ---------------- Phase 2: persistent HMMA scan ----------------
__global__ __launch_bounds__(NTHR, 1) void scan_kernel(
    const float* __restrict__ state,
    const float* __restrict__ W_hr, const float* __restrict__ W_hz,
    const float* __restrict__ W_hh,
    float* __restrict__ out)
{
    extern __shared__ char smem[];
    __shared__ int s_base;
    const int tid  = threadIdx.x;
    const int w    = tid >> 5, lane = tid & 31;
    const int g    = lane >> 2, c = lane & 3;
    const int cta  = blockIdx.x;
    const int j0   = cta * 8;

    if (tid == 0) s_base = g_phase;

    // ---- resident B fragments as uint4 (proven values, new packing) ----
#pragma unroll 1
    for (int i = 0; i < 16; i++) {
        const int nt = i >> 3;                 // 0 = W_hr, 1 = W_hz
        const int sg = (i & 7) * 8 + w;
        const float* __restrict__ W = nt ? W_hz : W_hr;
        const int col = j0 + g;
        const int k0 = sg * 16 + 2 * c;
        const float w0 = W[(size_t)k0 * H_ + col];
        const float w1 = W[(size_t)(k0 + 1) * H_ + col];
        const float w2 = W[(size_t)(k0 + 8) * H_ + col];
        const float w3 = W[(size_t)(k0 + 9) * H_ + col];
        uint32_t l0, l1;
        const uint32_t h0 = pack2(w0, w1, l0);
        const uint32_t h1 = pack2(w2, w3, l1);
        *(uint4*)(smem + BG + (uint32_t)(((nt * 64 + sg) * 32 + lane) * 16)) =
            make_uint4(h0, h1, l0, l1);
    }
#pragma unroll 1
    for (int i = 0; i < 8; i++) {
        const int sg = i * 8 + w;
        const int col = j0 + g;
        const int k0 = sg * 16 + 2 * c;
        const float w0 = W_hh[(size_t)k0 * H_ + col];
        const float w1 = W_hh[(size_t)(k0 + 1) * H_ + col];
        const float w2 = W_hh[(size_t)(k0 + 8) * H_ + col];
        const float w3 = W_hh[(size_t)(k0 + 9) * H_ + col];
        uint32_t l0, l1;
        const uint32_t h0 = pack2(w0, w1, l0);
        const uint32_t h1 = pack2(w2, w3, l1);
        *(uint4*)(smem + BC + (uint32_t)((sg * 32 + lane) * 16)) = make_uint4(h0, h1, l0, l1);
    }

    const int b1 = (w & 3) * 16 + g;
    const int b2 = b1 + 8;
    const int jj = j0 + 2 * c;
    // frag-write coordinates for this thread's epilogue outputs
    const int sgW   = cta >> 1;
    const int slotW = cta & 1;
    const int laneW = g * 4 + c;
    const uint32_t fidx = (uint32_t)(((w & 3) * 64 + sgW) * 32 + laneW);

    // ---- initial h -> fragment layout ----
    if (w < 4) {
        const float s00 = state[(size_t)b1 * H_ + jj];
        const float s01 = state[(size_t)b1 * H_ + jj + 1];
        const float s10 = state[(size_t)b2 * H_ + jj];
        const float s11 = state[(size_t)b2 * H_ + jj + 1];
        uint32_t l0, l1;
        const uint32_t h0 = pack2(s00, s01, l0);
        const uint32_t h1 = pack2(s10, s11, l1);
        ((uint2*)&g_hf_hi[fidx])[slotW] = make_uint2(h0, h1);
        ((uint2*)&g_hf_lo[fidx])[slotW] = make_uint2(l0, l1);
    }
    __syncthreads();
    const int base = s_base;
    grid_barrier(base + 1);

    const int mt   = w & 3;
    const int gate = w >> 2;        // phase A: 0 = R, 1 = Z
    const int half = w >> 2;        // phase B: K half

    for (int t = 0; t < T_; t++) {
        const float* __restrict__ h_in = t ? (out + (size_t)(t - 1) * BH) : state;
        const float* __restrict__ xr_t = g_xproj + (size_t)t * BH;
        const float* __restrict__ xz_t = g_xproj + TBH + (size_t)t * BH;
        const float* __restrict__ xh_t = g_xproj + 2 * TBH + (size_t)t * BH;

        // prefetch epilogue operands (covers DRAM latency under the mainloop)
        float2 ex0, ex1, h0p, h1p;
        if (w < 4) {
            ex0 = *(const float2*)(xr_t + (size_t)b1 * H_ + jj);
            ex1 = *(const float2*)(xr_t + (size_t)b2 * H_ + jj);
            h0p = *(const float2*)(h_in + (size_t)b1 * H_ + jj);
            h1p = *(const float2*)(h_in + (size_t)b2 * H_ + jj);
        } else {
            ex0 = *(const float2*)(xz_t + (size_t)b1 * H_ + jj);
            ex1 = *(const float2*)(xz_t + (size_t)b2 * H_ + jj);
        }

        // ===== phase A: R and Z gates =====
        float acc[4] = {0.f, 0.f, 0.f, 0.f};
        mm_run<64>(acc, g_hf_hi + mt * 64 * 32 + lane, g_hf_lo + mt * 64 * 32 + lane,
                   smem + BG + (uint32_t)gate * 32768u + lane * 16 - lane * 16 + (uint32_t)lane * 0,
                   lane);
        // NOTE: bp points at tile base; lane offset applied inside mm_run.

        if (w < 4) {   // R gate -> R*h fragments to global
            const float rh00 = sigf(acc[0] + ex0.x) * h0p.x;
            const float rh01 = sigf(acc[1] + ex0.y) * h0p.y;
            const float rh10 = sigf(acc[2] + ex1.x) * h1p.x;
            const float rh11 = sigf(acc[3] + ex1.y) * h1p.y;
            uint32_t l0, l1;
            const uint32_t h0 = pack2(rh00, rh01, l0);
            const uint32_t h1 = pack2(rh10, rh11, l1);
            ((uint2*)&g_rf_hi[fidx])[slotW] = make_uint2(h0, h1);
            ((uint2*)&g_rf_lo[fidx])[slotW] = make_uint2(l0, l1);
        } else {       // Z gate -> smem
            float2 z0, z1;
            z0.x = sigf(acc[0] + ex0.x); z0.y = sigf(acc[1] + ex0.y);
            z1.x = sigf(acc[2] + ex1.x); z1.y = sigf(acc[3] + ex1.y);
            *(float2*)(smem + ZB + (uint32_t)(b1 * 8 + 2 * c) * 4) = z0;
            *(float2*)(smem + ZB + (uint32_t)(b2 * 8 + 2 * c) * 4) = z1;
        }
        grid_barrier(base + 2 + 2 * t);   // g_rf complete everywhere

        // prefetch xh for epilogue B
        float2 xh0, xh1;
        if (w < 4) {
            xh0 = *(const float2*)(xh_t + (size_t)b1 * H_ + jj);
            xh1 = *(const float2*)(xh_t + (size_t)b2 * H_ + jj);
        }

        // ===== phase B: candidate + state update (K-split across warp halves) =====
        float acc2[4] = {0.f, 0.f, 0.f, 0.f};
        mm_run<32>(acc2, g_rf_hi + (mt * 64 + half * 32) * 32 + lane,
                   g_rf_lo + (mt * 64 + half * 32) * 32 + lane,
                   smem + BC + (uint32_t)half * 32u * 512u, lane);

        if (w >= 4) {
            *(float4*)(smem + RED + (uint32_t)(((w - 4) * 32 + lane) * 16)) =
                make_float4(acc2[0], acc2[1], acc2[2], acc2[3]);
        }
        __syncthreads();
        if (w < 4) {
            const float4 p = *(const float4*)(smem + RED + (uint32_t)((w * 32 + lane) * 16));
            acc2[0] += p.x; acc2[1] += p.y; acc2[2] += p.z; acc2[3] += p.w;

            const float2 z0 = *(const float2*)(smem + ZB + (uint32_t)(b1 * 8 + 2 * c) * 4);
            const float2 z1 = *(const float2*)(smem + ZB + (uint32_t)(b2 * 8 + 2 * c) * 4);

            const float v00 = z0.x * h0p.x + (1.f - z0.x) * tanhf(acc2[0] + xh0.x);
            const float v01 = z0.y * h0p.y + (1.f - z0.y) * tanhf(acc2[1] + xh0.y);
            const float v10 = z1.x * h1p.x + (1.f - z1.x) * tanhf(acc2[2] + xh1.x);
            const float v11 = z1.y * h1p.y + (1.f - z1.y) * tanhf(acc2[3] + xh1.y);

            float* out_t = out + (size_t)t * BH;
            *(float2*)(out_t + (size_t)b1 * H_ + jj) = make_float2(v00, v01);
            *(float2*)(out_t + (size_t)b2 * H_ + jj) = make_float2(v10, v11);

            uint32_t l0, l1;
            const uint32_t h0 = pack2(v00, v01, l0);
            const uint32_t h1 = pack2(v10, v11, l1);
            ((uint2*)&g_hf_hi[fidx])[slotW] = make_uint2(h0, h1);
            ((uint2*)&g_hf_lo[fidx])[slotW] = make_uint2(l0, l1);
        }
        grid_barrier(base + 3 + 2 * t);   // out[t] + g_hf complete everywhere
    }
}

// ---------------- host launcher ----------------
extern "C" void kernel_launch(void* const* d_in, const int* in_sizes, int n_in,
                              void* d_out, int out_size)
{
    (void)in_sizes; (void)n_in; (void)out_size;
    const float* X     = (const float*)d_in[0];
    const float* state = (const float*)d_in[1];
    const float* W_xr  = (const float*)d_in[2];
    const float* W_hr  = (const float*)d_in[3];
    const float* b_r   = (const float*)d_in[4];
    const float* W_xz  = (const float*)d_in[5];
    const float* W_hz  = (const float*)d_in[6];
    const float* b_z   = (const float*)d_in[7];
    const float* W_xh  = (const float*)d_in[8];
    const float* W_hh  = (const float*)d_in[9];
    const float* b_h   = (const float*)d_in[10];
    float* out = (float*)d_out;

    static int attr_set = 0;
    if (!attr_set) {
        cudaFuncSetAttribute(proj_mma_kernel,
                             cudaFuncAttributeMaxDynamicSharedMemorySize, (int)P_SMEM);
        cudaFuncSetAttribute(scan_kernel,
                             cudaFuncAttributeMaxDynamicSharedMemorySize, (int)SMEM_TOTAL);
        attr_set = 1;
    }

    conv_x_kernel<<<65536, 256>>>(X);
    pack_w_kernel<<<3072, 256>>>(W_xr, W_xz, W_xh);
    {
        dim3 grid(H_ / 128, (T_ * B_) / 128, 3);
        proj_mma_kernel<<<grid, 256, P_SMEM>>>(b_r, b_z, b_h);
    }

    scan_kernel<<<NCTA, NTHR, SMEM_TOTAL>>>(state, W_hr, W_hz, W_hh, out);

    cudaMemcpyAsync(out + TBH, out + TBH - BH, (size_t)BH * sizeof(float),
                    cudaMemcpyDeviceToDevice, 0);
}